// round 14
// baseline (speedup 1.0000x reference)
#include <cuda_runtime.h>
#include <math.h>
#include <stdint.h>

#define BATCH  8
#define CH     192
#define C3     576
#define NVOX   13824       // 24*24*24
#define HEADS  6
#define HD     32
#define EPSN   1e-12f
#define TSTRIDE (CH * 4608)   // per-batch T size (fits in g_V slot)

// Scratch
__device__ float g_Z[(size_t)BATCH * CH * NVOX];     // Z = Gw @ X (only q/k cols valid)
__device__ float g_V[(size_t)BATCH * NVOX * CH];     // reused as T[b][o][e*192+c]
__device__ float g_Gw[CH * CH];
__device__ float g_wb[CH];
__device__ float g_pwT[CH * CH];
__device__ float g_msum[BATCH * CH];
__device__ float g_c[4];                             // [0] = b2
__device__ float g_spart[BATCH * HEADS * 12 * 1152];
__device__ float g_M[BATCH * CH * CH];

// ---------------------------------------------------------------------------
__device__ __forceinline__ unsigned f2tf(float f) {
    unsigned u;
    asm("cvt.rna.tf32.f32 %0, %1;" : "=r"(u) : "f"(f));
    return u;
}
__device__ __forceinline__ void mma_tf32(float* c, const unsigned* a, const unsigned* b) {
    asm volatile(
        "mma.sync.aligned.m16n8k8.row.col.f32.tf32.tf32.f32 "
        "{%0,%1,%2,%3},{%4,%5,%6,%7},{%8,%9},{%0,%1,%2,%3};"
        : "+f"(c[0]), "+f"(c[1]), "+f"(c[2]), "+f"(c[3])
        : "r"(a[0]), "r"(a[1]), "r"(a[2]), "r"(a[3]), "r"(b[0]), "r"(b[1]));
}
__device__ __forceinline__ uint32_t smem_u32(const void* p) {
    uint32_t a;
    asm("{ .reg .u64 t; cvta.to.shared.u64 t, %1; cvt.u32.u64 %0, t; }" : "=r"(a) : "l"(p));
    return a;
}
__device__ __forceinline__ void ldsm_x4(unsigned* r, uint32_t addr) {
    asm volatile("ldmatrix.sync.aligned.m8n8.x4.shared.b16 {%0,%1,%2,%3}, [%4];"
        : "=r"(r[0]), "=r"(r[1]), "=r"(r[2]), "=r"(r[3]) : "r"(addr));
}
__device__ __forceinline__ void ldsm_x2(unsigned* r, uint32_t addr) {
    asm volatile("ldmatrix.sync.aligned.m8n8.x2.shared.b16 {%0,%1}, [%2];"
        : "=r"(r[0]), "=r"(r[1]) : "r"(addr));
}

// ---------------------------------------------------------------------------
// K0 merged prekernel: blocks 0..35 Gw tiles; 36..71 pwT tiles; 72 wb+b2.
// ---------------------------------------------------------------------------
__global__ __launch_bounds__(256) void pre_kernel(const float* __restrict__ w,
                                                  const float* __restrict__ beta,
                                                  const float* __restrict__ pw)
{
    __shared__ float sh[2112];
    const int bid = blockIdx.x;
    const int t = threadIdx.x;

    if (bid < 36) {
        float (*Wi)[33] = (float (*)[33])sh;
        float (*Wj)[33] = (float (*)[33])(sh + 1056);
        const int i0 = (bid % 6) * 32, j0 = (bid / 6) * 32;
        const int ti = t & 31, tj = (t >> 5) * 4;
        float acc[4] = {0.f, 0.f, 0.f, 0.f};
        for (int a0 = 0; a0 < C3; a0 += 32) {
            __syncthreads();
#pragma unroll
            for (int l = 0; l < 4; l++) {
                const int a = (t >> 5) + 8 * l, c = t & 31;
                Wi[a][c] = w[(a0 + a) * CH + i0 + c];
                Wj[a][c] = w[(a0 + a) * CH + j0 + c];
            }
            __syncthreads();
#pragma unroll
            for (int a = 0; a < 32; a++) {
                const float wi = Wi[a][ti];
#pragma unroll
                for (int r = 0; r < 4; r++) acc[r] += wi * Wj[a][tj + r];
            }
        }
#pragma unroll
        for (int r = 0; r < 4; r++) g_Gw[(i0 + ti) * CH + j0 + tj + r] = acc[r];
    } else if (bid < 72) {
        float (*tile)[33] = (float (*)[33])sh;
        const int bb = bid - 36;
        const int bx = (bb % 6) * 32, by = (bb / 6) * 32;
        const int tx = t & 31, ty = t >> 5;
#pragma unroll
        for (int l = 0; l < 4; l++)
            tile[ty + 8 * l][tx] = pw[(by + ty + 8 * l) * CH + bx + tx];
        __syncthreads();
#pragma unroll
        for (int l = 0; l < 4; l++)
            g_pwT[(bx + ty + 8 * l) * CH + by + tx] = tile[tx][ty + 8 * l];
    } else {
        if (t < CH) {
            float s = 0.f;
            for (int a = 0; a < C3; a++) s += beta[a] * w[a * CH + t];
            g_wb[t] = s;
        }
        if (t < 64) {
            float p = 0.f;
            for (int a = t; a < C3; a += 64) p += beta[a] * beta[a];
            sh[t] = p;
        }
        __syncthreads();
        if (t == 0) {
            float s = 0.f;
            for (int i = 0; i < 64; i++) s += sh[i];
            g_c[0] = s;
        }
    }
}

// ---------------------------------------------------------------------------
// K1: Z[b] = Gw @ X[b], columns 576e + 96j, j<4.
// BM=192, BN=96, BK=16, 256 thr, warp 48x48, 2 CTA/SM.
// ---------------------------------------------------------------------------
__global__ __launch_bounds__(256, 2) void z_gemm(const float* __restrict__ x)
{
    __shared__ unsigned As[2][192 * 20];
    __shared__ unsigned Bs[2][16 * 104];

    const int b = blockIdx.z;
    const int e = blockIdx.x >> 2, j = blockIdx.x & 3;
    const int n0 = 576 * e + 96 * j;
    const int t = threadIdx.x;
    const int wid = t >> 5, lane = t & 31;
    const int wm = wid & 3, wn = wid >> 2;
    const int gid = lane >> 2, tid4 = lane & 3;

    const float* bsrc = x + (size_t)b * CH * NVOX + n0;
    float* zb = g_Z + (size_t)b * CH * NVOX + n0;

    const uint32_t sAs = smem_u32(As);
    const uint32_t aoff = (uint32_t)((((lane & 7) + ((lane >> 3) & 1) * 8) * 20 +
                                      ((lane >> 4) * 4)) * 4);

    float acc[3][6][4];
#pragma unroll
    for (int i = 0; i < 3; i++)
#pragma unroll
        for (int q = 0; q < 6; q++)
#pragma unroll
            for (int r = 0; r < 4; r++) acc[i][q][r] = 0.f;

    float4 ar[3], br[2];
#define LDA_Z(K0) { _Pragma("unroll") for (int l = 0; l < 3; l++) {                      \
                      const int idx = l * 256 + t;                                       \
                      ar[l] = *(const float4*)(g_Gw + (idx >> 2) * CH + (K0) + (idx & 3) * 4); } }
#define LDB_Z(K0) { _Pragma("unroll") for (int l = 0; l < 2; l++) {                      \
                      const int idx = l * 256 + t;                                       \
                      if (idx < 384)                                                     \
                        br[l] = *(const float4*)(bsrc + (size_t)((K0) + idx / 24) * NVOX + (idx % 24) * 4); } }
#define STA_G(ST) { _Pragma("unroll") for (int l = 0; l < 3; l++) {                      \
                      const int idx = l * 256 + t;                                       \
                      unsigned* d = &As[ST][(idx >> 2) * 20 + (idx & 3) * 4];            \
                      d[0]=f2tf(ar[l].x); d[1]=f2tf(ar[l].y); d[2]=f2tf(ar[l].z); d[3]=f2tf(ar[l].w); } }
#define STB_G(ST) { _Pragma("unroll") for (int l = 0; l < 2; l++) {                      \
                      const int idx = l * 256 + t;                                       \
                      if (idx < 384) {                                                   \
                        unsigned* d = &Bs[ST][(idx / 24) * 104 + (idx % 24) * 4];        \
                        d[0]=f2tf(br[l].x); d[1]=f2tf(br[l].y); d[2]=f2tf(br[l].z); d[3]=f2tf(br[l].w); } } }

    LDA_Z(0); LDB_Z(0);
    STA_G(0); STB_G(0);
    LDA_Z(16); LDB_Z(16);
    __syncthreads();

    for (int it = 0; it < 12; it++) {
        const int st = it & 1;
        if (it < 11) { STA_G(st ^ 1); STB_G(st ^ 1); }
        if (it < 10) { LDA_Z(16 * (it + 2)); LDB_Z(16 * (it + 2)); }

        const unsigned* Bsl = Bs[st];
        const uint32_t aBase = sAs + (uint32_t)(st * 3840 * 4) + aoff;
#pragma unroll
        for (int h = 0; h < 2; h++) {
            const int kk = h * 8;
            unsigned af[3][4], bf[6][2];
#pragma unroll
            for (int mt = 0; mt < 3; mt++) {
                const int r0 = wm * 48 + mt * 16;
                ldsm_x4(af[mt], aBase + (uint32_t)((r0 * 20 + kk) * 4));
            }
#pragma unroll
            for (int nt = 0; nt < 6; nt++) {
                const int col = wn * 48 + nt * 8 + gid;
                bf[nt][0] = Bsl[(kk + tid4) * 104 + col];
                bf[nt][1] = Bsl[(kk + tid4 + 4) * 104 + col];
            }
#pragma unroll
            for (int mt = 0; mt < 3; mt++)
#pragma unroll
                for (int nt = 0; nt < 6; nt++)
                    mma_tf32(acc[mt][nt], af[mt], bf[nt]);
        }
        __syncthreads();
    }

#pragma unroll
    for (int mt = 0; mt < 3; mt++) {
        const int r0 = wm * 48 + mt * 16 + gid;
#pragma unroll
        for (int nt = 0; nt < 6; nt++) {
            const int col = wn * 48 + nt * 8 + 2 * tid4;
            *(float2*)(zb + (size_t)r0 * NVOX + col) = make_float2(acc[mt][nt][0], acc[mt][nt][1]);
            *(float2*)(zb + (size_t)(r0 + 8) * NVOX + col) = make_float2(acc[mt][nt][2], acc[mt][nt][3]);
        }
    }
}

// ---------------------------------------------------------------------------
// K3: score partials v2. grid (12, H, B), 256 thr.
// ---------------------------------------------------------------------------
__global__ __launch_bounds__(256) void scores_kernel(const float* __restrict__ x)
{
    __shared__ float Xq[2][32][36], Zq[2][32][36], Xk[2][32][36], Zk[2][32][36];
    __shared__ float wbs[32];
    __shared__ float Sh[2][32][32];

    const int isl = blockIdx.x >> 1, ep = blockIdx.x & 1;
    const int h = blockIdx.y, b = blockIdx.z;
    const int i0 = isl * 32, e0 = ep * 12;
    const int t = threadIdx.x;
    const int wid = t >> 5, lane = t & 31;
    const int h32 = h * 32;

    const float* xb = x + (size_t)b * CH * NVOX;
    const float* zb = g_Z + (size_t)b * CH * NVOX;

    if (t < 32) wbs[t] = g_wb[i0 + t];

    const int li  = t >> 3;
    const int lc4 = (t & 7) << 2;

    const int ihalf = wid >> 1;
    const int sig = (wid & 1) * 32 + lane;
    const int ccg = sig >> 3;
    const int d0c = (sig & 7) << 2;

    float s[4][4];
#pragma unroll
    for (int a = 0; a < 4; a++)
#pragma unroll
        for (int q = 0; q < 4; q++) s[a][q] = 0.f;
    float dac = 0.f, wac = 0.f;

    const size_t rowoff = (size_t)(i0 + li) * NVOX;
    float4 rq, rzq, rk, rzk;
    {
        const int u = 576 * e0 + h32 + lc4;
        rq  = *(const float4*)(xb + rowoff + u);
        rzq = *(const float4*)(zb + rowoff + u);
        rk  = *(const float4*)(xb + rowoff + u + 192);
        rzk = *(const float4*)(zb + rowoff + u + 192);
    }
    *(float4*)&Xq[0][li][lc4] = rq;  *(float4*)&Zq[0][li][lc4] = rzq;
    *(float4*)&Xk[0][li][lc4] = rk;  *(float4*)&Zk[0][li][lc4] = rzk;
    __syncthreads();

    for (int e = 0; e < 12; e++) {
        const int cur = e & 1, nxt = cur ^ 1;
        if (e < 11) {
            const int u = 576 * (e0 + e + 1) + h32 + lc4;
            rq  = *(const float4*)(xb + rowoff + u);
            rzq = *(const float4*)(zb + rowoff + u);
            rk  = *(const float4*)(xb + rowoff + u + 192);
            rzk = *(const float4*)(zb + rowoff + u + 192);
        }
        if (wid < 4) {
            const int ib = ihalf * 16;
#pragma unroll
            for (int ii = 0; ii < 16; ii++) {
                const int i = ib + ii;
                const float4 zv = *(const float4*)&Zk[cur][i][d0c];
                const float q0 = Xq[cur][i][ccg];
                const float q1 = Xq[cur][i][ccg + 8];
                const float q2 = Xq[cur][i][ccg + 16];
                const float q3 = Xq[cur][i][ccg + 24];
                s[0][0] += q0 * zv.x; s[0][1] += q0 * zv.y; s[0][2] += q0 * zv.z; s[0][3] += q0 * zv.w;
                s[1][0] += q1 * zv.x; s[1][1] += q1 * zv.y; s[1][2] += q1 * zv.z; s[1][3] += q1 * zv.w;
                s[2][0] += q2 * zv.x; s[2][1] += q2 * zv.y; s[2][2] += q2 * zv.z; s[2][3] += q2 * zv.w;
                s[3][0] += q3 * zv.x; s[3][1] += q3 * zv.y; s[3][2] += q3 * zv.z; s[3][3] += q3 * zv.w;
            }
        } else if (wid == 4) {
#pragma unroll
            for (int i = 0; i < 32; i++) {
                const float xv = Xq[cur][i][lane];
                dac += xv * Zq[cur][i][lane];
                wac += wbs[i] * xv;
            }
        } else if (wid == 5) {
#pragma unroll
            for (int i = 0; i < 32; i++) {
                const float xv = Xk[cur][i][lane];
                dac += xv * Zk[cur][i][lane];
                wac += wbs[i] * xv;
            }
        }
        if (e < 11) {
            *(float4*)&Xq[nxt][li][lc4] = rq;  *(float4*)&Zq[nxt][li][lc4] = rzq;
            *(float4*)&Xk[nxt][li][lc4] = rk;  *(float4*)&Zk[nxt][li][lc4] = rzk;
        }
        __syncthreads();
    }

    if (wid < 4) {
#pragma unroll
        for (int a = 0; a < 4; a++)
            *(float4*)&Sh[ihalf][ccg + 8 * a][d0c] =
                make_float4(s[a][0], s[a][1], s[a][2], s[a][3]);
    }
    __syncthreads();

    float* sp = g_spart + (size_t)((b * HEADS + h) * 12 + blockIdx.x) * 1152;
    {
        const int eidx = t * 4;
        const float* s0 = &Sh[0][0][0];
        const float* s1 = &Sh[1][0][0];
        float4 a = *(const float4*)(s0 + eidx);
        float4 c = *(const float4*)(s1 + eidx);
        sp[eidx + 0] = a.x + c.x;
        sp[eidx + 1] = a.y + c.y;
        sp[eidx + 2] = a.z + c.z;
        sp[eidx + 3] = a.w + c.w;
    }
    if (wid == 4) { sp[1024 + lane] = dac; sp[1088 + lane] = wac; }
    if (wid == 5) { sp[1056 + lane] = dac; sp[1120 + lane] = wac; }
}

// ---------------------------------------------------------------------------
// K4 (fused): reduce partials + softmax -> attn (smem) -> mmix -> g_M
// grid (HEADS, BATCH), 256 thr.
// ---------------------------------------------------------------------------
__global__ __launch_bounds__(256) void softmax_mmix_kernel(const float* __restrict__ temp)
{
    __shared__ float sS[1024];
    __shared__ float snq[32], snk[32], swq[32], swk[32];
    __shared__ float att[32][32];

    const int h = blockIdx.x, b = blockIdx.y;
    const int t = threadIdx.x;
    const float b2 = g_c[0];
    const float* sp = g_spart + (size_t)((b * HEADS + h) * 12) * 1152;

#pragma unroll
    for (int i = 0; i < 4; i++) {
        const int e = t + i * 256;
        float a = 0.f;
        for (int s = 0; s < 12; s++) a += sp[s * 1152 + e];
        sS[e] = a;
    }
    if (t < 64) {
        float d = 0.f, wv = 0.f;
        const int od = 1024 + t, ow = 1088 + t;
        for (int s = 0; s < 12; s++) { d += sp[s * 1152 + od]; wv += sp[s * 1152 + ow]; }
        const float n2 = d + 2.f * wv + 24.f * b2;
        const float r = fmaxf(sqrtf(fmaxf(n2, 0.f)), EPSN);
        if (t < 32) { snq[t] = r; swq[t] = wv; }
        else        { snk[t - 32] = r; swk[t - 32] = wv; }
    }
    __syncthreads();

    const int w = t >> 5, lane = t & 31;
    const float tv = temp[h];

    for (int r = 0; r < 4; r++) {
        const int c = w * 4 + r;
        const float Sfull = sS[c * 32 + lane] + swq[c] + swk[lane] + 24.f * b2;
        float L = Sfull / (snq[c] * snk[lane]) * tv;
        float mx = L;
#pragma unroll
        for (int o = 16; o > 0; o >>= 1) mx = fmaxf(mx, __shfl_xor_sync(0xffffffffu, mx, o));
        const float ev = expf(L - mx);
        float sm = ev;
#pragma unroll
        for (int o = 16; o > 0; o >>= 1) sm += __shfl_xor_sync(0xffffffffu, sm, o);
        att[c][lane] = ev / sm;
    }
    __syncthreads();

    // mmix part: M[b][o][h*32+d] = sum_cc pwT[cc*6+h][o] * att[cc][d]
    if (t < CH) {
        float s[32];
#pragma unroll
        for (int d = 0; d < 32; d++) s[d] = 0.f;
#pragma unroll 8
        for (int cc = 0; cc < 32; cc++) {
            const float v = g_pwT[(cc * HEADS + h) * CH + t];
#pragma unroll
            for (int d4 = 0; d4 < 8; d4++) {
                const float4 a = *(const float4*)&att[cc][d4 * 4];
                s[d4 * 4 + 0] += v * a.x;
                s[d4 * 4 + 1] += v * a.y;
                s[d4 * 4 + 2] += v * a.z;
                s[d4 * 4 + 3] += v * a.w;
            }
        }
        float* Mb = g_M + (size_t)b * CH * CH + t * CH + h * HD;
#pragma unroll
        for (int d = 0; d < 32; d++) Mb[d] = s[d];
    }
}

// K5b: msum[b][o] = sum_k M[o][k]
__global__ __launch_bounds__(192) void msum_kernel()
{
    const int b = blockIdx.x, t = threadIdx.x;
    const float* Mb = g_M + (size_t)b * CH * CH + (size_t)t * CH;
    float s = 0.f;
#pragma unroll 4
    for (int k = 0; k < CH; k += 4) {
        const float4 v = *(const float4*)(Mb + k);
        s += v.x + v.y + v.z + v.w;
    }
    g_msum[b * CH + t] = s;
}

// ---------------------------------------------------------------------------
// K6a (t_gemm): T[b][o][e*192+c] = sum_k M[o,k] * X[c, 576e+384+k]
// BM=96 (c rows, split by blockIdx.y), BN=96 (o cols), K=192.
// 8 warps = 2m x 4n, warp tile 48x24 (3x3). grid (48, 2, 8).
// ---------------------------------------------------------------------------
__global__ __launch_bounds__(256, 2) void t_gemm(const float* __restrict__ x)
{
    __shared__ unsigned As[2][96 * 20];
    __shared__ unsigned Bs[2][96 * 20];

    const int b  = blockIdx.z;
    const int e  = blockIdx.x >> 1;
    const int oB = (blockIdx.x & 1) * 96;
    const int ch = blockIdx.y;           // c half: 0 or 1
    const int t  = threadIdx.x;
    const int wid = t >> 5, lane = t & 31;
    const int wm = wid & 1, wn = wid >> 1;   // 2m x 4n
    const int gid = lane >> 2, tid4 = lane & 3;

    const float* Asrc = x + (size_t)b * CH * NVOX + (size_t)(ch * 96) * NVOX + 576 * e + 384;
    const float* Bsrc = g_M + (size_t)b * CH * CH + (size_t)oB * CH;
    float* Tb = g_V + (size_t)b * TSTRIDE;

    const uint32_t sAs = smem_u32(As);
    const uint32_t sBs = smem_u32(Bs);
    const uint32_t aoff = (uint32_t)((((lane & 7) + ((lane >> 3) & 1) * 8) * 20 +
                                      ((lane >> 4) * 4)) * 4);
    const uint32_t boff = (uint32_t)(((lane & 7) * 20 + ((lane >> 3) & 1) * 4) * 4);

    float acc[3][3][4];
#pragma unroll
    for (int i = 0; i < 3; i++)
#pragma unroll
        for (int q = 0; q < 3; q++)
#pragma unroll
            for (int r = 0; r < 4; r++) acc[i][q][r] = 0.f;

    float4 ar[2], br[2];
#define LDA_T2(K0) { _Pragma("unroll") for (int l = 0; l < 2; l++) {                     \
                       const int idx = l * 256 + t;                                      \
                       if (idx < 384)                                                    \
                         ar[l] = *(const float4*)(Asrc + (size_t)(idx >> 2) * NVOX + (K0) + (idx & 3) * 4); } }
#define LDB_T2(K0) { _Pragma("unroll") for (int l = 0; l < 2; l++) {                     \
                       const int idx = l * 256 + t;                                      \
                       if (idx < 384)                                                    \
                         br[l] = *(const float4*)(Bsrc + (size_t)(idx >> 2) * CH + (K0) + (idx & 3) * 4); } }
#define STA_T2(ST) { _Pragma("unroll") for (int l = 0; l < 2; l++) {                     \
                       const int idx = l * 256 + t;                                      \
                       if (idx < 384) {                                                  \
                         unsigned* d = &As[ST][(idx >> 2) * 20 + (idx & 3) * 4];         \
                         d[0]=f2tf(ar[l].x); d[1]=f2tf(ar[l].y); d[2]=f2tf(ar[l].z); d[3]=f2tf(ar[l].w); } } }
#define STB_T2(ST) { _Pragma("unroll") for (int l = 0; l < 2; l++) {                     \
                       const int idx = l * 256 + t;                                      \
                       if (idx < 384) {                                                  \
                         unsigned* d = &Bs[ST][(idx >> 2) * 20 + (idx & 3) * 4];         \
                         d[0]=f2tf(br[l].x); d[1]=f2tf(br[l].y); d[2]=f2tf(br[l].z); d[3]=f2tf(br[l].w); } } }

    LDA_T2(0); LDB_T2(0);
    STA_T2(0); STB_T2(0);
    LDA_T2(16); LDB_T2(16);
    __syncthreads();

    for (int it = 0; it < 12; it++) {
        const int st = it & 1;
        if (it < 11) { STA_T2(st ^ 1); STB_T2(st ^ 1); }
        if (it < 10) { LDA_T2(16 * (it + 2)); LDB_T2(16 * (it + 2)); }

        const uint32_t aBase = sAs + (uint32_t)(st * 1920 * 4) + aoff;
        const uint32_t bBase = sBs + (uint32_t)(st * 1920 * 4) + boff;
#pragma unroll
        for (int h = 0; h < 2; h++) {
            const int kk = h * 8;
            unsigned af[3][4], bf[3][2];
#pragma unroll
            for (int mt = 0; mt < 3; mt++) {
                const int r0 = wm * 48 + mt * 16;
                ldsm_x4(af[mt], aBase + (uint32_t)((r0 * 20 + kk) * 4));
            }
#pragma unroll
            for (int nt = 0; nt < 3; nt++) {
                const int c0 = wn * 24 + nt * 8;
                ldsm_x2(bf[nt], bBase + (uint32_t)((c0 * 20 + kk) * 4));
            }
#pragma unroll
            for (int mt = 0; mt < 3; mt++)
#pragma unroll
                for (int nt = 0; nt < 3; nt++)
                    mma_tf32(acc[mt][nt], af[mt], bf[nt]);
        }
        __syncthreads();
    }

#pragma unroll
    for (int mt = 0; mt < 3; mt++) {
        const int c0 = ch * 96 + wm * 48 + mt * 16 + gid;
#pragma unroll
        for (int nt = 0; nt < 3; nt++) {
            const int o0 = oB + wn * 24 + nt * 8 + 2 * tid4;
            float* p0 = Tb + (size_t)o0 * 4608 + e * 192;
            float* p1 = Tb + (size_t)(o0 + 1) * 4608 + e * 192;
            p0[c0]     = acc[mt][nt][0];
            p1[c0]     = acc[mt][nt][1];
            p0[c0 + 8] = acc[mt][nt][2];
            p1[c0 + 8] = acc[mt][nt][3];
        }
    }
}

// ---------------------------------------------------------------------------
// K6b (y_gemm): y[o][24a+e] = sum_c W[a,c]*T[o][e*192+c] + msum[o]*beta[a] + pbias[o]
// BM=192, BN=96 (4 o x 24 e), K=192. grid (48, 3, 8).
// ---------------------------------------------------------------------------
__global__ __launch_bounds__(256, 2) void y_gemm(float* __restrict__ y,
                                                 const float* __restrict__ qkv_w,
                                                 const float* __restrict__ qkv_b,
                                                 const float* __restrict__ pbias)
{
    __shared__ unsigned As[2][192 * 20];
    __shared__ unsigned Bs[2][96 * 20];

    const int b  = blockIdx.z;
    const int m0 = blockIdx.y * 192;
    const int cb = blockIdx.x;           // 0..47 -> o base = cb*4
    const int t  = threadIdx.x;
    const int wid = t >> 5, lane = t & 31;
    const int wm = wid & 3, wn = wid >> 2;
    const int gid = lane >> 2, tid4 = lane & 3;

    const float* Asrc = qkv_w + (size_t)m0 * CH;
    const float* Tb = g_V + (size_t)b * TSTRIDE + (size_t)cb * 4 * 4608;
    float* yb = y + (size_t)b * CH * NVOX;

    const uint32_t sAs = smem_u32(As);
    const uint32_t sBs = smem_u32(Bs);
    const uint32_t aoff = (uint32_t)((((lane & 7) + ((lane >> 3) & 1) * 8) * 20 +
                                      ((lane >> 4) * 4)) * 4);
    const uint32_t boff = (uint32_t)(((lane & 7) * 20 + ((lane >> 3) & 1) * 4) * 4);

    float acc[3][6][4];
#pragma unroll
    for (int i = 0; i < 3; i++)
#pragma unroll
        for (int q = 0; q < 6; q++)
#pragma unroll
            for (int r = 0; r < 4; r++) acc[i][q][r] = 0.f;

    float4 ar[3], br[2];
#define LDA_Y(K0) { _Pragma("unroll") for (int l = 0; l < 3; l++) {                      \
                      const int idx = l * 256 + t;                                       \
                      ar[l] = *(const float4*)(Asrc + (size_t)(idx >> 2) * CH + (K0) + (idx & 3) * 4); } }
#define LDB_Y(K0) { _Pragma("unroll") for (int l = 0; l < 2; l++) {                      \
                      const int idx = l * 256 + t;                                       \
                      if (idx < 384) {                                                   \
                        const int jj = idx >> 2;                                         \
                        br[l] = *(const float4*)(Tb + (size_t)(jj / 24) * 4608 +         \
                                                 (jj % 24) * 192 + (K0) + (idx & 3) * 4); } } }
#define STA_Y(ST) { _Pragma("unroll") for (int l = 0; l < 3; l++) {                      \
                      const int idx = l * 256 + t;                                       \
                      unsigned* d = &As[ST][(idx >> 2) * 20 + (idx & 3) * 4];            \
                      d[0]=f2tf(ar[l].x); d[1]=f2tf(ar[l].y); d[2]=f2tf(ar[l].z); d[3]=f2tf(ar[l].w); } }
#define STB_Y(ST) { _Pragma("unroll") for (int l = 0; l < 2; l++) {                      \
                      const int idx = l * 256 + t;                                       \
                      if (idx < 384) {                                                   \
                        unsigned* d = &Bs[ST][(idx >> 2) * 20 + (idx & 3) * 4];          \
                        d[0]=f2tf(br[l].x); d[1]=f2tf(br[l].y); d[2]=f2tf(br[l].z); d[3]=f2tf(br[l].w); } } }

    LDA_Y(0); LDB_Y(0);
    STA_Y(0); STB_Y(0);
    LDA_Y(16); LDB_Y(16);
    __syncthreads();

    for (int it = 0; it < 12; it++) {
        const int st = it & 1;
        if (it < 11) { STA_Y(st ^ 1); STB_Y(st ^ 1); }
        if (it < 10) { LDA_Y(16 * (it + 2)); LDB_Y(16 * (it + 2)); }

        const uint32_t aBase = sAs + (uint32_t)(st * 3840 * 4) + aoff;
        const uint32_t bBase = sBs + (uint32_t)(st * 1920 * 4) + boff;
#pragma unroll
        for (int h = 0; h < 2; h++) {
            const int kk = h * 8;
            unsigned af[3][4], bf[6][2];
#pragma unroll
            for (int mt = 0; mt < 3; mt++) {
                const int r0 = wm * 48 + mt * 16;
                ldsm_x4(af[mt], aBase + (uint32_t)((r0 * 20 + kk) * 4));
            }
#pragma unroll
            for (int nt = 0; nt < 6; nt++) {
                const int c0 = wn * 48 + nt * 8;
                ldsm_x2(bf[nt], bBase + (uint32_t)((c0 * 20 + kk) * 4));
            }
#pragma unroll
            for (int mt = 0; mt < 3; mt++)
#pragma unroll
                for (int nt = 0; nt < 6; nt++)
                    mma_tf32(acc[mt][nt], af[mt], bf[nt]);
        }
        __syncthreads();
    }

#pragma unroll
    for (int mt = 0; mt < 3; mt++) {
        const int r0 = wm * 48 + mt * 16 + gid;
        const int a0 = m0 + r0;
        const float be0 = qkv_b[a0], be1 = qkv_b[a0 + 8];
#pragma unroll
        for (int nt = 0; nt < 6; nt++) {
            const int j0 = wn * 48 + nt * 8 + 2 * tid4;
            const int o  = cb * 4 + j0 / 24;
            const int e  = j0 % 24;
            const float ms = g_msum[b * CH + o];
            const float pb = pbias[o];
            const float bias0 = ms * be0 + pb;
            const float bias1 = ms * be1 + pb;
            *(float2*)(yb + (size_t)o * NVOX + 24 * a0 + e) =
                make_float2(acc[mt][nt][0] + bias0, acc[mt][nt][1] + bias0);
            *(float2*)(yb + (size_t)o * NVOX + 24 * (a0 + 8) + e) =
                make_float2(acc[mt][nt][2] + bias1, acc[mt][nt][3] + bias1);
        }
    }
}

// ---------------------------------------------------------------------------
extern "C" void kernel_launch(void* const* d_in, const int* in_sizes, int n_in,
                              void* d_out, int out_size)
{
    const float* x      = (const float*)d_in[0];
    const float* qkv_w  = (const float*)d_in[1];
    const float* qkv_b  = (const float*)d_in[2];
    const float* temp   = (const float*)d_in[3];
    const float* proj_w = (const float*)d_in[4];
    const float* proj_b = (const float*)d_in[5];
    float* y = (float*)d_out;

    pre_kernel        <<<73, 256>>>(qkv_w, qkv_b, proj_w);
    z_gemm            <<<dim3(96, 1, BATCH), 256>>>(x);
    scores_kernel     <<<dim3(12, HEADS, BATCH), 256>>>(x);
    softmax_mmix_kernel<<<dim3(HEADS, BATCH), 256>>>(temp);
    msum_kernel       <<<BATCH, 192>>>();
    t_gemm            <<<dim3(48, 2, BATCH), 256>>>(x);
    y_gemm            <<<dim3(48, 3, BATCH), 256>>>(y, qkv_b ? qkv_w : qkv_w, qkv_b, proj_b);
}

// round 15
// speedup vs baseline: 1.0114x; 1.0114x over previous
#include <cuda_runtime.h>
#include <math.h>
#include <stdint.h>

#define BATCH  8
#define CH     192
#define C3     576
#define NVOX   13824       // 24*24*24
#define HEADS  6
#define HD     32
#define EPSN   1e-12f
#define TSTRIDE (CH * 4608)   // per-batch T size (fits in g_V slot)

// Scratch
__device__ float g_Z[(size_t)BATCH * CH * NVOX];     // Z = Gw @ X (only q/k cols valid)
__device__ float g_V[(size_t)BATCH * NVOX * CH];     // reused as T[b][o][e*192+c]
__device__ float g_Gw[CH * CH];
__device__ float g_wb[CH];
__device__ float g_pwT[CH * CH];
__device__ float g_msum[BATCH * CH];
__device__ float g_c[4];                             // [0] = b2
__device__ float g_spart[BATCH * HEADS * 12 * 1152];
__device__ float g_M[BATCH * CH * CH];

// ---------------------------------------------------------------------------
__device__ __forceinline__ unsigned f2tf(float f) {
    unsigned u;
    asm("cvt.rna.tf32.f32 %0, %1;" : "=r"(u) : "f"(f));
    return u;
}
__device__ __forceinline__ void mma_tf32(float* c, const unsigned* a, const unsigned* b) {
    asm volatile(
        "mma.sync.aligned.m16n8k8.row.col.f32.tf32.tf32.f32 "
        "{%0,%1,%2,%3},{%4,%5,%6,%7},{%8,%9},{%0,%1,%2,%3};"
        : "+f"(c[0]), "+f"(c[1]), "+f"(c[2]), "+f"(c[3])
        : "r"(a[0]), "r"(a[1]), "r"(a[2]), "r"(a[3]), "r"(b[0]), "r"(b[1]));
}
__device__ __forceinline__ uint32_t smem_u32(const void* p) {
    uint32_t a;
    asm("{ .reg .u64 t; cvta.to.shared.u64 t, %1; cvt.u32.u64 %0, t; }" : "=r"(a) : "l"(p));
    return a;
}
__device__ __forceinline__ void ldsm_x4(unsigned* r, uint32_t addr) {
    asm volatile("ldmatrix.sync.aligned.m8n8.x4.shared.b16 {%0,%1,%2,%3}, [%4];"
        : "=r"(r[0]), "=r"(r[1]), "=r"(r[2]), "=r"(r[3]) : "r"(addr));
}
__device__ __forceinline__ void ldsm_x2(unsigned* r, uint32_t addr) {
    asm volatile("ldmatrix.sync.aligned.m8n8.x2.shared.b16 {%0,%1}, [%2];"
        : "=r"(r[0]), "=r"(r[1]) : "r"(addr));
}

// ---------------------------------------------------------------------------
// K0 merged prekernel: blocks 0..35 Gw tiles; 36..71 pwT tiles; 72 wb+b2.
// ---------------------------------------------------------------------------
__global__ __launch_bounds__(256) void pre_kernel(const float* __restrict__ w,
                                                  const float* __restrict__ beta,
                                                  const float* __restrict__ pw)
{
    __shared__ float sh[2112];
    const int bid = blockIdx.x;
    const int t = threadIdx.x;

    if (bid < 36) {
        float (*Wi)[33] = (float (*)[33])sh;
        float (*Wj)[33] = (float (*)[33])(sh + 1056);
        const int i0 = (bid % 6) * 32, j0 = (bid / 6) * 32;
        const int ti = t & 31, tj = (t >> 5) * 4;
        float acc[4] = {0.f, 0.f, 0.f, 0.f};
        for (int a0 = 0; a0 < C3; a0 += 32) {
            __syncthreads();
#pragma unroll
            for (int l = 0; l < 4; l++) {
                const int a = (t >> 5) + 8 * l, c = t & 31;
                Wi[a][c] = w[(a0 + a) * CH + i0 + c];
                Wj[a][c] = w[(a0 + a) * CH + j0 + c];
            }
            __syncthreads();
#pragma unroll
            for (int a = 0; a < 32; a++) {
                const float wi = Wi[a][ti];
#pragma unroll
                for (int r = 0; r < 4; r++) acc[r] += wi * Wj[a][tj + r];
            }
        }
#pragma unroll
        for (int r = 0; r < 4; r++) g_Gw[(i0 + ti) * CH + j0 + tj + r] = acc[r];
    } else if (bid < 72) {
        float (*tile)[33] = (float (*)[33])sh;
        const int bb = bid - 36;
        const int bx = (bb % 6) * 32, by = (bb / 6) * 32;
        const int tx = t & 31, ty = t >> 5;
#pragma unroll
        for (int l = 0; l < 4; l++)
            tile[ty + 8 * l][tx] = pw[(by + ty + 8 * l) * CH + bx + tx];
        __syncthreads();
#pragma unroll
        for (int l = 0; l < 4; l++)
            g_pwT[(bx + ty + 8 * l) * CH + by + tx] = tile[tx][ty + 8 * l];
    } else {
        if (t < CH) {
            float s = 0.f;
            for (int a = 0; a < C3; a++) s += beta[a] * w[a * CH + t];
            g_wb[t] = s;
        }
        if (t < 64) {
            float p = 0.f;
            for (int a = t; a < C3; a += 64) p += beta[a] * beta[a];
            sh[t] = p;
        }
        __syncthreads();
        if (t == 0) {
            float s = 0.f;
            for (int i = 0; i < 64; i++) s += sh[i];
            g_c[0] = s;
        }
    }
}

// ---------------------------------------------------------------------------
// K1: Z[b] = Gw @ X[b], columns 576e + 96j, j<4.
// BM=192, BN=96, BK=16, 256 thr, warp 48x48, 2 CTA/SM.
// ---------------------------------------------------------------------------
__global__ __launch_bounds__(256, 2) void z_gemm(const float* __restrict__ x)
{
    __shared__ unsigned As[2][192 * 20];
    __shared__ unsigned Bs[2][16 * 104];

    const int b = blockIdx.z;
    const int e = blockIdx.x >> 2, j = blockIdx.x & 3;
    const int n0 = 576 * e + 96 * j;
    const int t = threadIdx.x;
    const int wid = t >> 5, lane = t & 31;
    const int wm = wid & 3, wn = wid >> 2;
    const int gid = lane >> 2, tid4 = lane & 3;

    const float* bsrc = x + (size_t)b * CH * NVOX + n0;
    float* zb = g_Z + (size_t)b * CH * NVOX + n0;

    const uint32_t sAs = smem_u32(As);
    const uint32_t aoff = (uint32_t)((((lane & 7) + ((lane >> 3) & 1) * 8) * 20 +
                                      ((lane >> 4) * 4)) * 4);

    float acc[3][6][4];
#pragma unroll
    for (int i = 0; i < 3; i++)
#pragma unroll
        for (int q = 0; q < 6; q++)
#pragma unroll
            for (int r = 0; r < 4; r++) acc[i][q][r] = 0.f;

    float4 ar[3], br[2];
#define LDA_Z(K0) { _Pragma("unroll") for (int l = 0; l < 3; l++) {                      \
                      const int idx = l * 256 + t;                                       \
                      ar[l] = *(const float4*)(g_Gw + (idx >> 2) * CH + (K0) + (idx & 3) * 4); } }
#define LDB_Z(K0) { _Pragma("unroll") for (int l = 0; l < 2; l++) {                      \
                      const int idx = l * 256 + t;                                       \
                      if (idx < 384)                                                     \
                        br[l] = *(const float4*)(bsrc + (size_t)((K0) + idx / 24) * NVOX + (idx % 24) * 4); } }
#define STA_G(ST) { _Pragma("unroll") for (int l = 0; l < 3; l++) {                      \
                      const int idx = l * 256 + t;                                       \
                      unsigned* d = &As[ST][(idx >> 2) * 20 + (idx & 3) * 4];            \
                      d[0]=f2tf(ar[l].x); d[1]=f2tf(ar[l].y); d[2]=f2tf(ar[l].z); d[3]=f2tf(ar[l].w); } }
#define STB_G(ST) { _Pragma("unroll") for (int l = 0; l < 2; l++) {                      \
                      const int idx = l * 256 + t;                                       \
                      if (idx < 384) {                                                   \
                        unsigned* d = &Bs[ST][(idx / 24) * 104 + (idx % 24) * 4];        \
                        d[0]=f2tf(br[l].x); d[1]=f2tf(br[l].y); d[2]=f2tf(br[l].z); d[3]=f2tf(br[l].w); } } }

    LDA_Z(0); LDB_Z(0);
    STA_G(0); STB_G(0);
    LDA_Z(16); LDB_Z(16);
    __syncthreads();

    for (int it = 0; it < 12; it++) {
        const int st = it & 1;
        if (it < 11) { STA_G(st ^ 1); STB_G(st ^ 1); }
        if (it < 10) { LDA_Z(16 * (it + 2)); LDB_Z(16 * (it + 2)); }

        const unsigned* Bsl = Bs[st];
        const uint32_t aBase = sAs + (uint32_t)(st * 3840 * 4) + aoff;
#pragma unroll
        for (int h = 0; h < 2; h++) {
            const int kk = h * 8;
            unsigned af[3][4], bf[6][2];
#pragma unroll
            for (int mt = 0; mt < 3; mt++) {
                const int r0 = wm * 48 + mt * 16;
                ldsm_x4(af[mt], aBase + (uint32_t)((r0 * 20 + kk) * 4));
            }
#pragma unroll
            for (int nt = 0; nt < 6; nt++) {
                const int col = wn * 48 + nt * 8 + gid;
                bf[nt][0] = Bsl[(kk + tid4) * 104 + col];
                bf[nt][1] = Bsl[(kk + tid4 + 4) * 104 + col];
            }
#pragma unroll
            for (int mt = 0; mt < 3; mt++)
#pragma unroll
                for (int nt = 0; nt < 6; nt++)
                    mma_tf32(acc[mt][nt], af[mt], bf[nt]);
        }
        __syncthreads();
    }

#pragma unroll
    for (int mt = 0; mt < 3; mt++) {
        const int r0 = wm * 48 + mt * 16 + gid;
#pragma unroll
        for (int nt = 0; nt < 6; nt++) {
            const int col = wn * 48 + nt * 8 + 2 * tid4;
            *(float2*)(zb + (size_t)r0 * NVOX + col) = make_float2(acc[mt][nt][0], acc[mt][nt][1]);
            *(float2*)(zb + (size_t)(r0 + 8) * NVOX + col) = make_float2(acc[mt][nt][2], acc[mt][nt][3]);
        }
    }
}

// ---------------------------------------------------------------------------
// K3: score partials v2. grid (12, H, B), 256 thr.
// ---------------------------------------------------------------------------
__global__ __launch_bounds__(256) void scores_kernel(const float* __restrict__ x)
{
    __shared__ float Xq[2][32][36], Zq[2][32][36], Xk[2][32][36], Zk[2][32][36];
    __shared__ float wbs[32];
    __shared__ float Sh[2][32][32];

    const int isl = blockIdx.x >> 1, ep = blockIdx.x & 1;
    const int h = blockIdx.y, b = blockIdx.z;
    const int i0 = isl * 32, e0 = ep * 12;
    const int t = threadIdx.x;
    const int wid = t >> 5, lane = t & 31;
    const int h32 = h * 32;

    const float* xb = x + (size_t)b * CH * NVOX;
    const float* zb = g_Z + (size_t)b * CH * NVOX;

    if (t < 32) wbs[t] = g_wb[i0 + t];

    const int li  = t >> 3;
    const int lc4 = (t & 7) << 2;

    const int ihalf = wid >> 1;
    const int sig = (wid & 1) * 32 + lane;
    const int ccg = sig >> 3;
    const int d0c = (sig & 7) << 2;

    float s[4][4];
#pragma unroll
    for (int a = 0; a < 4; a++)
#pragma unroll
        for (int q = 0; q < 4; q++) s[a][q] = 0.f;
    float dac = 0.f, wac = 0.f;

    const size_t rowoff = (size_t)(i0 + li) * NVOX;
    float4 rq, rzq, rk, rzk;
    {
        const int u = 576 * e0 + h32 + lc4;
        rq  = *(const float4*)(xb + rowoff + u);
        rzq = *(const float4*)(zb + rowoff + u);
        rk  = *(const float4*)(xb + rowoff + u + 192);
        rzk = *(const float4*)(zb + rowoff + u + 192);
    }
    *(float4*)&Xq[0][li][lc4] = rq;  *(float4*)&Zq[0][li][lc4] = rzq;
    *(float4*)&Xk[0][li][lc4] = rk;  *(float4*)&Zk[0][li][lc4] = rzk;
    __syncthreads();

    for (int e = 0; e < 12; e++) {
        const int cur = e & 1, nxt = cur ^ 1;
        if (e < 11) {
            const int u = 576 * (e0 + e + 1) + h32 + lc4;
            rq  = *(const float4*)(xb + rowoff + u);
            rzq = *(const float4*)(zb + rowoff + u);
            rk  = *(const float4*)(xb + rowoff + u + 192);
            rzk = *(const float4*)(zb + rowoff + u + 192);
        }
        if (wid < 4) {
            const int ib = ihalf * 16;
#pragma unroll
            for (int ii = 0; ii < 16; ii++) {
                const int i = ib + ii;
                const float4 zv = *(const float4*)&Zk[cur][i][d0c];
                const float q0 = Xq[cur][i][ccg];
                const float q1 = Xq[cur][i][ccg + 8];
                const float q2 = Xq[cur][i][ccg + 16];
                const float q3 = Xq[cur][i][ccg + 24];
                s[0][0] += q0 * zv.x; s[0][1] += q0 * zv.y; s[0][2] += q0 * zv.z; s[0][3] += q0 * zv.w;
                s[1][0] += q1 * zv.x; s[1][1] += q1 * zv.y; s[1][2] += q1 * zv.z; s[1][3] += q1 * zv.w;
                s[2][0] += q2 * zv.x; s[2][1] += q2 * zv.y; s[2][2] += q2 * zv.z; s[2][3] += q2 * zv.w;
                s[3][0] += q3 * zv.x; s[3][1] += q3 * zv.y; s[3][2] += q3 * zv.z; s[3][3] += q3 * zv.w;
            }
        } else if (wid == 4) {
#pragma unroll
            for (int i = 0; i < 32; i++) {
                const float xv = Xq[cur][i][lane];
                dac += xv * Zq[cur][i][lane];
                wac += wbs[i] * xv;
            }
        } else if (wid == 5) {
#pragma unroll
            for (int i = 0; i < 32; i++) {
                const float xv = Xk[cur][i][lane];
                dac += xv * Zk[cur][i][lane];
                wac += wbs[i] * xv;
            }
        }
        if (e < 11) {
            *(float4*)&Xq[nxt][li][lc4] = rq;  *(float4*)&Zq[nxt][li][lc4] = rzq;
            *(float4*)&Xk[nxt][li][lc4] = rk;  *(float4*)&Zk[nxt][li][lc4] = rzk;
        }
        __syncthreads();
    }

    if (wid < 4) {
#pragma unroll
        for (int a = 0; a < 4; a++)
            *(float4*)&Sh[ihalf][ccg + 8 * a][d0c] =
                make_float4(s[a][0], s[a][1], s[a][2], s[a][3]);
    }
    __syncthreads();

    float* sp = g_spart + (size_t)((b * HEADS + h) * 12 + blockIdx.x) * 1152;
    {
        const int eidx = t * 4;
        const float* s0 = &Sh[0][0][0];
        const float* s1 = &Sh[1][0][0];
        float4 a = *(const float4*)(s0 + eidx);
        float4 c = *(const float4*)(s1 + eidx);
        sp[eidx + 0] = a.x + c.x;
        sp[eidx + 1] = a.y + c.y;
        sp[eidx + 2] = a.z + c.z;
        sp[eidx + 3] = a.w + c.w;
    }
    if (wid == 4) { sp[1024 + lane] = dac; sp[1088 + lane] = wac; }
    if (wid == 5) { sp[1056 + lane] = dac; sp[1120 + lane] = wac; }
}

// ---------------------------------------------------------------------------
// K4 (fused): prefetch pwr regs -> reduce partials + softmax (smem) -> mmix.
// grid (HEADS, BATCH), 256 thr.
// ---------------------------------------------------------------------------
__global__ __launch_bounds__(256) void softmax_mmix_kernel(const float* __restrict__ temp)
{
    __shared__ float sS[1024];
    __shared__ float snq[32], snk[32], swq[32], swk[32];
    __shared__ float att[32][32];

    const int h = blockIdx.x, b = blockIdx.y;
    const int t = threadIdx.x;
    const float b2 = g_c[0];
    const float* sp = g_spart + (size_t)((b * HEADS + h) * 12) * 1152;

    // Prefetch mmix weights early: independent of softmax, hides LDG latency.
    float pwr[32];
    if (t < CH) {
#pragma unroll
        for (int cc = 0; cc < 32; cc++)
            pwr[cc] = g_pwT[(cc * HEADS + h) * CH + t];
    }

#pragma unroll
    for (int i = 0; i < 4; i++) {
        const int e = t + i * 256;
        float a = 0.f;
        for (int s = 0; s < 12; s++) a += sp[s * 1152 + e];
        sS[e] = a;
    }
    if (t < 64) {
        float d = 0.f, wv = 0.f;
        const int od = 1024 + t, ow = 1088 + t;
        for (int s = 0; s < 12; s++) { d += sp[s * 1152 + od]; wv += sp[s * 1152 + ow]; }
        const float n2 = d + 2.f * wv + 24.f * b2;
        const float r = fmaxf(sqrtf(fmaxf(n2, 0.f)), EPSN);
        if (t < 32) { snq[t] = r; swq[t] = wv; }
        else        { snk[t - 32] = r; swk[t - 32] = wv; }
    }
    __syncthreads();

    const int w = t >> 5, lane = t & 31;
    const float tv = temp[h];

    for (int r = 0; r < 4; r++) {
        const int c = w * 4 + r;
        const float Sfull = sS[c * 32 + lane] + swq[c] + swk[lane] + 24.f * b2;
        float L = Sfull / (snq[c] * snk[lane]) * tv;
        float mx = L;
#pragma unroll
        for (int o = 16; o > 0; o >>= 1) mx = fmaxf(mx, __shfl_xor_sync(0xffffffffu, mx, o));
        const float ev = expf(L - mx);
        float sm = ev;
#pragma unroll
        for (int o = 16; o > 0; o >>= 1) sm += __shfl_xor_sync(0xffffffffu, sm, o);
        att[c][lane] = ev / sm;
    }
    __syncthreads();

    // mmix: M[b][o][h*32+d] = sum_cc pwr[cc] * att[cc][d]
    if (t < CH) {
        float s[32];
#pragma unroll
        for (int d = 0; d < 32; d++) s[d] = 0.f;
#pragma unroll 8
        for (int cc = 0; cc < 32; cc++) {
            const float v = pwr[cc];
#pragma unroll
            for (int d4 = 0; d4 < 8; d4++) {
                const float4 a = *(const float4*)&att[cc][d4 * 4];
                s[d4 * 4 + 0] += v * a.x;
                s[d4 * 4 + 1] += v * a.y;
                s[d4 * 4 + 2] += v * a.z;
                s[d4 * 4 + 3] += v * a.w;
            }
        }
        float* Mb = g_M + (size_t)b * CH * CH + t * CH + h * HD;
#pragma unroll
        for (int d = 0; d < 32; d++) Mb[d] = s[d];
    }
}

// K5b: msum[b][o] = sum_k M[o][k]
__global__ __launch_bounds__(192) void msum_kernel()
{
    const int b = blockIdx.x, t = threadIdx.x;
    const float* Mb = g_M + (size_t)b * CH * CH + (size_t)t * CH;
    float s = 0.f;
#pragma unroll 4
    for (int k = 0; k < CH; k += 4) {
        const float4 v = *(const float4*)(Mb + k);
        s += v.x + v.y + v.z + v.w;
    }
    g_msum[b * CH + t] = s;
}

// ---------------------------------------------------------------------------
// K6a (t_gemm): T[b][o][e*192+c] = sum_k M[o,k] * X[c, 576e+384+k]
// BM=96 (c rows, split by blockIdx.y), BN=96 (o cols), K=192.
// 8 warps = 2m x 4n, warp tile 48x24 (3x3). grid (48, 2, 8).
// ---------------------------------------------------------------------------
__global__ __launch_bounds__(256, 2) void t_gemm(const float* __restrict__ x)
{
    __shared__ unsigned As[2][96 * 20];
    __shared__ unsigned Bs[2][96 * 20];

    const int b  = blockIdx.z;
    const int e  = blockIdx.x >> 1;
    const int oB = (blockIdx.x & 1) * 96;
    const int ch = blockIdx.y;           // c half: 0 or 1
    const int t  = threadIdx.x;
    const int wid = t >> 5, lane = t & 31;
    const int wm = wid & 1, wn = wid >> 1;   // 2m x 4n
    const int gid = lane >> 2, tid4 = lane & 3;

    const float* Asrc = x + (size_t)b * CH * NVOX + (size_t)(ch * 96) * NVOX + 576 * e + 384;
    const float* Bsrc = g_M + (size_t)b * CH * CH + (size_t)oB * CH;
    float* Tb = g_V + (size_t)b * TSTRIDE;

    const uint32_t sAs = smem_u32(As);
    const uint32_t sBs = smem_u32(Bs);
    const uint32_t aoff = (uint32_t)((((lane & 7) + ((lane >> 3) & 1) * 8) * 20 +
                                      ((lane >> 4) * 4)) * 4);
    const uint32_t boff = (uint32_t)(((lane & 7) * 20 + ((lane >> 3) & 1) * 4) * 4);

    float acc[3][3][4];
#pragma unroll
    for (int i = 0; i < 3; i++)
#pragma unroll
        for (int q = 0; q < 3; q++)
#pragma unroll
            for (int r = 0; r < 4; r++) acc[i][q][r] = 0.f;

    float4 ar[2], br[2];
#define LDA_T2(K0) { _Pragma("unroll") for (int l = 0; l < 2; l++) {                     \
                       const int idx = l * 256 + t;                                      \
                       if (idx < 384)                                                    \
                         ar[l] = *(const float4*)(Asrc + (size_t)(idx >> 2) * NVOX + (K0) + (idx & 3) * 4); } }
#define LDB_T2(K0) { _Pragma("unroll") for (int l = 0; l < 2; l++) {                     \
                       const int idx = l * 256 + t;                                      \
                       if (idx < 384)                                                    \
                         br[l] = *(const float4*)(Bsrc + (size_t)(idx >> 2) * CH + (K0) + (idx & 3) * 4); } }
#define STA_T2(ST) { _Pragma("unroll") for (int l = 0; l < 2; l++) {                     \
                       const int idx = l * 256 + t;                                      \
                       if (idx < 384) {                                                  \
                         unsigned* d = &As[ST][(idx >> 2) * 20 + (idx & 3) * 4];         \
                         d[0]=f2tf(ar[l].x); d[1]=f2tf(ar[l].y); d[2]=f2tf(ar[l].z); d[3]=f2tf(ar[l].w); } } }
#define STB_T2(ST) { _Pragma("unroll") for (int l = 0; l < 2; l++) {                     \
                       const int idx = l * 256 + t;                                      \
                       if (idx < 384) {                                                  \
                         unsigned* d = &Bs[ST][(idx >> 2) * 20 + (idx & 3) * 4];         \
                         d[0]=f2tf(br[l].x); d[1]=f2tf(br[l].y); d[2]=f2tf(br[l].z); d[3]=f2tf(br[l].w); } } }

    LDA_T2(0); LDB_T2(0);
    STA_T2(0); STB_T2(0);
    LDA_T2(16); LDB_T2(16);
    __syncthreads();

    for (int it = 0; it < 12; it++) {
        const int st = it & 1;
        if (it < 11) { STA_T2(st ^ 1); STB_T2(st ^ 1); }
        if (it < 10) { LDA_T2(16 * (it + 2)); LDB_T2(16 * (it + 2)); }

        const uint32_t aBase = sAs + (uint32_t)(st * 1920 * 4) + aoff;
        const uint32_t bBase = sBs + (uint32_t)(st * 1920 * 4) + boff;
#pragma unroll
        for (int h = 0; h < 2; h++) {
            const int kk = h * 8;
            unsigned af[3][4], bf[3][2];
#pragma unroll
            for (int mt = 0; mt < 3; mt++) {
                const int r0 = wm * 48 + mt * 16;
                ldsm_x4(af[mt], aBase + (uint32_t)((r0 * 20 + kk) * 4));
            }
#pragma unroll
            for (int nt = 0; nt < 3; nt++) {
                const int c0 = wn * 24 + nt * 8;
                ldsm_x2(bf[nt], bBase + (uint32_t)((c0 * 20 + kk) * 4));
            }
#pragma unroll
            for (int mt = 0; mt < 3; mt++)
#pragma unroll
                for (int nt = 0; nt < 3; nt++)
                    mma_tf32(acc[mt][nt], af[mt], bf[nt]);
        }
        __syncthreads();
    }

#pragma unroll
    for (int mt = 0; mt < 3; mt++) {
        const int c0 = ch * 96 + wm * 48 + mt * 16 + gid;
#pragma unroll
        for (int nt = 0; nt < 3; nt++) {
            const int o0 = oB + wn * 24 + nt * 8 + 2 * tid4;
            float* p0 = Tb + (size_t)o0 * 4608 + e * 192;
            float* p1 = Tb + (size_t)(o0 + 1) * 4608 + e * 192;
            p0[c0]     = acc[mt][nt][0];
            p1[c0]     = acc[mt][nt][1];
            p0[c0 + 8] = acc[mt][nt][2];
            p1[c0 + 8] = acc[mt][nt][3];
        }
    }
}

// ---------------------------------------------------------------------------
// K6b (y_gemm): y[o][24a+e] = sum_c W[a,c]*T[o][e*192+c] + msum[o]*beta[a] + pbias[o]
// BM=192, BN=96 (4 o x 24 e), K=192. grid (48, 3, 8).
// ---------------------------------------------------------------------------
__global__ __launch_bounds__(256, 2) void y_gemm(float* __restrict__ y,
                                                 const float* __restrict__ qkv_w,
                                                 const float* __restrict__ qkv_b,
                                                 const float* __restrict__ pbias)
{
    __shared__ unsigned As[2][192 * 20];
    __shared__ unsigned Bs[2][96 * 20];

    const int b  = blockIdx.z;
    const int m0 = blockIdx.y * 192;
    const int cb = blockIdx.x;           // 0..47 -> o base = cb*4
    const int t  = threadIdx.x;
    const int wid = t >> 5, lane = t & 31;
    const int wm = wid & 3, wn = wid >> 2;
    const int gid = lane >> 2, tid4 = lane & 3;

    const float* Asrc = qkv_w + (size_t)m0 * CH;
    const float* Tb = g_V + (size_t)b * TSTRIDE + (size_t)cb * 4 * 4608;
    float* yb = y + (size_t)b * CH * NVOX;

    const uint32_t sAs = smem_u32(As);
    const uint32_t sBs = smem_u32(Bs);
    const uint32_t aoff = (uint32_t)((((lane & 7) + ((lane >> 3) & 1) * 8) * 20 +
                                      ((lane >> 4) * 4)) * 4);
    const uint32_t boff = (uint32_t)(((lane & 7) * 20 + ((lane >> 3) & 1) * 4) * 4);

    float acc[3][6][4];
#pragma unroll
    for (int i = 0; i < 3; i++)
#pragma unroll
        for (int q = 0; q < 6; q++)
#pragma unroll
            for (int r = 0; r < 4; r++) acc[i][q][r] = 0.f;

    float4 ar[3], br[2];
#define LDA_Y(K0) { _Pragma("unroll") for (int l = 0; l < 3; l++) {                      \
                      const int idx = l * 256 + t;                                       \
                      ar[l] = *(const float4*)(Asrc + (size_t)(idx >> 2) * CH + (K0) + (idx & 3) * 4); } }
#define LDB_Y(K0) { _Pragma("unroll") for (int l = 0; l < 2; l++) {                      \
                      const int idx = l * 256 + t;                                       \
                      if (idx < 384) {                                                   \
                        const int jj = idx >> 2;                                         \
                        br[l] = *(const float4*)(Tb + (size_t)(jj / 24) * 4608 +         \
                                                 (jj % 24) * 192 + (K0) + (idx & 3) * 4); } } }
#define STA_Y(ST) { _Pragma("unroll") for (int l = 0; l < 3; l++) {                      \
                      const int idx = l * 256 + t;                                       \
                      unsigned* d = &As[ST][(idx >> 2) * 20 + (idx & 3) * 4];            \
                      d[0]=f2tf(ar[l].x); d[1]=f2tf(ar[l].y); d[2]=f2tf(ar[l].z); d[3]=f2tf(ar[l].w); } }
#define STB_Y(ST) { _Pragma("unroll") for (int l = 0; l < 2; l++) {                      \
                      const int idx = l * 256 + t;                                       \
                      if (idx < 384) {                                                   \
                        unsigned* d = &Bs[ST][(idx >> 2) * 20 + (idx & 3) * 4];          \
                        d[0]=f2tf(br[l].x); d[1]=f2tf(br[l].y); d[2]=f2tf(br[l].z); d[3]=f2tf(br[l].w); } } }

    LDA_Y(0); LDB_Y(0);
    STA_Y(0); STB_Y(0);
    LDA_Y(16); LDB_Y(16);
    __syncthreads();

    for (int it = 0; it < 12; it++) {
        const int st = it & 1;
        if (it < 11) { STA_Y(st ^ 1); STB_Y(st ^ 1); }
        if (it < 10) { LDA_Y(16 * (it + 2)); LDB_Y(16 * (it + 2)); }

        const uint32_t aBase = sAs + (uint32_t)(st * 3840 * 4) + aoff;
        const uint32_t bBase = sBs + (uint32_t)(st * 1920 * 4) + boff;
#pragma unroll
        for (int h = 0; h < 2; h++) {
            const int kk = h * 8;
            unsigned af[3][4], bf[6][2];
#pragma unroll
            for (int mt = 0; mt < 3; mt++) {
                const int r0 = wm * 48 + mt * 16;
                ldsm_x4(af[mt], aBase + (uint32_t)((r0 * 20 + kk) * 4));
            }
#pragma unroll
            for (int nt = 0; nt < 6; nt++) {
                const int c0 = wn * 48 + nt * 8;
                ldsm_x2(bf[nt], bBase + (uint32_t)((c0 * 20 + kk) * 4));
            }
#pragma unroll
            for (int mt = 0; mt < 3; mt++)
#pragma unroll
                for (int nt = 0; nt < 6; nt++)
                    mma_tf32(acc[mt][nt], af[mt], bf[nt]);
        }
        __syncthreads();
    }

#pragma unroll
    for (int mt = 0; mt < 3; mt++) {
        const int r0 = wm * 48 + mt * 16 + gid;
        const int a0 = m0 + r0;
        const float be0 = qkv_b[a0], be1 = qkv_b[a0 + 8];
#pragma unroll
        for (int nt = 0; nt < 6; nt++) {
            const int j0 = wn * 48 + nt * 8 + 2 * tid4;
            const int o  = cb * 4 + j0 / 24;
            const int e  = j0 % 24;
            const float ms = g_msum[b * CH + o];
            const float pb = pbias[o];
            const float bias0 = ms * be0 + pb;
            const float bias1 = ms * be1 + pb;
            *(float2*)(yb + (size_t)o * NVOX + 24 * a0 + e) =
                make_float2(acc[mt][nt][0] + bias0, acc[mt][nt][1] + bias0);
            *(float2*)(yb + (size_t)o * NVOX + 24 * (a0 + 8) + e) =
                make_float2(acc[mt][nt][2] + bias1, acc[mt][nt][3] + bias1);
        }
    }
}

// ---------------------------------------------------------------------------
extern "C" void kernel_launch(void* const* d_in, const int* in_sizes, int n_in,
                              void* d_out, int out_size)
{
    const float* x      = (const float*)d_in[0];
    const float* qkv_w  = (const float*)d_in[1];
    const float* qkv_b  = (const float*)d_in[2];
    const float* temp   = (const float*)d_in[3];
    const float* proj_w = (const float*)d_in[4];
    const float* proj_b = (const float*)d_in[5];
    float* y = (float*)d_out;

    pre_kernel         <<<73, 256>>>(qkv_w, qkv_b, proj_w);
    z_gemm             <<<dim3(96, 1, BATCH), 256>>>(x);
    scores_kernel      <<<dim3(12, HEADS, BATCH), 256>>>(x);
    softmax_mmix_kernel<<<dim3(HEADS, BATCH), 256>>>(temp);
    msum_kernel        <<<BATCH, 192>>>();
    t_gemm             <<<dim3(48, 2, BATCH), 256>>>(x);
    y_gemm             <<<dim3(48, 3, BATCH), 256>>>(y, qkv_w, qkv_b, proj_b);
}

// round 16
// speedup vs baseline: 1.0490x; 1.0372x over previous
#include <cuda_runtime.h>
#include <math.h>
#include <stdint.h>

#define BATCH  8
#define CH     192
#define C3     576
#define NVOX   13824       // 24*24*24
#define HEADS  6
#define HD     32
#define EPSN   1e-12f
#define TSTRIDE (CH * 4608)   // per-batch T size (fits in g_V slot)

// Scratch
__device__ float g_Z[(size_t)BATCH * CH * NVOX];     // Z = Gw @ X (only q/k cols valid)
__device__ float g_V[(size_t)BATCH * NVOX * CH];     // reused as T[b][o][e*192+c]
__device__ float g_Gw[CH * CH];
__device__ float g_wb[CH];
__device__ float g_pwT[CH * CH];
__device__ float g_msum[CH];                         // = row sums of proj_w (input-indep!)
__device__ float g_c[4];                             // [0] = b2
__device__ float g_spart[BATCH * HEADS * 12 * 1152];
__device__ float g_M[BATCH * CH * CH];

// ---------------------------------------------------------------------------
__device__ __forceinline__ unsigned f2tf(float f) {
    unsigned u;
    asm("cvt.rna.tf32.f32 %0, %1;" : "=r"(u) : "f"(f));
    return u;
}
__device__ __forceinline__ void mma_tf32(float* c, const unsigned* a, const unsigned* b) {
    asm volatile(
        "mma.sync.aligned.m16n8k8.row.col.f32.tf32.tf32.f32 "
        "{%0,%1,%2,%3},{%4,%5,%6,%7},{%8,%9},{%0,%1,%2,%3};"
        : "+f"(c[0]), "+f"(c[1]), "+f"(c[2]), "+f"(c[3])
        : "r"(a[0]), "r"(a[1]), "r"(a[2]), "r"(a[3]), "r"(b[0]), "r"(b[1]));
}
__device__ __forceinline__ uint32_t smem_u32(const void* p) {
    uint32_t a;
    asm("{ .reg .u64 t; cvta.to.shared.u64 t, %1; cvt.u32.u64 %0, t; }" : "=r"(a) : "l"(p));
    return a;
}
__device__ __forceinline__ void ldsm_x4(unsigned* r, uint32_t addr) {
    asm volatile("ldmatrix.sync.aligned.m8n8.x4.shared.b16 {%0,%1,%2,%3}, [%4];"
        : "=r"(r[0]), "=r"(r[1]), "=r"(r[2]), "=r"(r[3]) : "r"(addr));
}
__device__ __forceinline__ void ldsm_x2(unsigned* r, uint32_t addr) {
    asm volatile("ldmatrix.sync.aligned.m8n8.x2.shared.b16 {%0,%1}, [%2];"
        : "=r"(r[0]), "=r"(r[1]) : "r"(addr));
}

// ---------------------------------------------------------------------------
// K0 merged prekernel: blocks 0..35 Gw tiles; 36..71 pwT tiles; 72 wb+b2+msum.
// ---------------------------------------------------------------------------
__global__ __launch_bounds__(256) void pre_kernel(const float* __restrict__ w,
                                                  const float* __restrict__ beta,
                                                  const float* __restrict__ pw)
{
    __shared__ float sh[2112];
    const int bid = blockIdx.x;
    const int t = threadIdx.x;

    if (bid < 36) {
        float (*Wi)[33] = (float (*)[33])sh;
        float (*Wj)[33] = (float (*)[33])(sh + 1056);
        const int i0 = (bid % 6) * 32, j0 = (bid / 6) * 32;
        const int ti = t & 31, tj = (t >> 5) * 4;
        float acc[4] = {0.f, 0.f, 0.f, 0.f};
        for (int a0 = 0; a0 < C3; a0 += 32) {
            __syncthreads();
#pragma unroll
            for (int l = 0; l < 4; l++) {
                const int a = (t >> 5) + 8 * l, c = t & 31;
                Wi[a][c] = w[(a0 + a) * CH + i0 + c];
                Wj[a][c] = w[(a0 + a) * CH + j0 + c];
            }
            __syncthreads();
#pragma unroll
            for (int a = 0; a < 32; a++) {
                const float wi = Wi[a][ti];
#pragma unroll
                for (int r = 0; r < 4; r++) acc[r] += wi * Wj[a][tj + r];
            }
        }
#pragma unroll
        for (int r = 0; r < 4; r++) g_Gw[(i0 + ti) * CH + j0 + tj + r] = acc[r];
    } else if (bid < 72) {
        float (*tile)[33] = (float (*)[33])sh;
        const int bb = bid - 36;
        const int bx = (bb % 6) * 32, by = (bb / 6) * 32;
        const int tx = t & 31, ty = t >> 5;
#pragma unroll
        for (int l = 0; l < 4; l++)
            tile[ty + 8 * l][tx] = pw[(by + ty + 8 * l) * CH + bx + tx];
        __syncthreads();
#pragma unroll
        for (int l = 0; l < 4; l++)
            g_pwT[(bx + ty + 8 * l) * CH + by + tx] = tile[tx][ty + 8 * l];
    } else {
        if (t < CH) {
            float s = 0.f;
            for (int a = 0; a < C3; a++) s += beta[a] * w[a * CH + t];
            g_wb[t] = s;
            // msum[o] = sum_c proj_w[o][c]  (softmax rows sum to 1 -> exact)
            float ms = 0.f;
#pragma unroll 4
            for (int c = 0; c < CH; c += 4) {
                const float4 v = *(const float4*)(pw + (size_t)t * CH + c);
                ms += v.x + v.y + v.z + v.w;
            }
            g_msum[t] = ms;
        }
        if (t < 64) {
            float p = 0.f;
            for (int a = t; a < C3; a += 64) p += beta[a] * beta[a];
            sh[t] = p;
        }
        __syncthreads();
        if (t == 0) {
            float s = 0.f;
            for (int i = 0; i < 64; i++) s += sh[i];
            g_c[0] = s;
        }
    }
}

// ---------------------------------------------------------------------------
// K1: Z[b] = Gw @ X[b], columns 576e + 96j, j<4.
// BM=192, BN=96, BK=16, 256 thr, warp 48x48, 2 CTA/SM.
// ---------------------------------------------------------------------------
__global__ __launch_bounds__(256, 2) void z_gemm(const float* __restrict__ x)
{
    __shared__ unsigned As[2][192 * 20];
    __shared__ unsigned Bs[2][16 * 104];

    const int b = blockIdx.z;
    const int e = blockIdx.x >> 2, j = blockIdx.x & 3;
    const int n0 = 576 * e + 96 * j;
    const int t = threadIdx.x;
    const int wid = t >> 5, lane = t & 31;
    const int wm = wid & 3, wn = wid >> 2;
    const int gid = lane >> 2, tid4 = lane & 3;

    const float* bsrc = x + (size_t)b * CH * NVOX + n0;
    float* zb = g_Z + (size_t)b * CH * NVOX + n0;

    const uint32_t sAs = smem_u32(As);
    const uint32_t aoff = (uint32_t)((((lane & 7) + ((lane >> 3) & 1) * 8) * 20 +
                                      ((lane >> 4) * 4)) * 4);

    float acc[3][6][4];
#pragma unroll
    for (int i = 0; i < 3; i++)
#pragma unroll
        for (int q = 0; q < 6; q++)
#pragma unroll
            for (int r = 0; r < 4; r++) acc[i][q][r] = 0.f;

    float4 ar[3], br[2];
#define LDA_Z(K0) { _Pragma("unroll") for (int l = 0; l < 3; l++) {                      \
                      const int idx = l * 256 + t;                                       \
                      ar[l] = *(const float4*)(g_Gw + (idx >> 2) * CH + (K0) + (idx & 3) * 4); } }
#define LDB_Z(K0) { _Pragma("unroll") for (int l = 0; l < 2; l++) {                      \
                      const int idx = l * 256 + t;                                       \
                      if (idx < 384)                                                     \
                        br[l] = *(const float4*)(bsrc + (size_t)((K0) + idx / 24) * NVOX + (idx % 24) * 4); } }
#define STA_G(ST) { _Pragma("unroll") for (int l = 0; l < 3; l++) {                      \
                      const int idx = l * 256 + t;                                       \
                      unsigned* d = &As[ST][(idx >> 2) * 20 + (idx & 3) * 4];            \
                      d[0]=f2tf(ar[l].x); d[1]=f2tf(ar[l].y); d[2]=f2tf(ar[l].z); d[3]=f2tf(ar[l].w); } }
#define STB_G(ST) { _Pragma("unroll") for (int l = 0; l < 2; l++) {                      \
                      const int idx = l * 256 + t;                                       \
                      if (idx < 384) {                                                   \
                        unsigned* d = &Bs[ST][(idx / 24) * 104 + (idx % 24) * 4];        \
                        d[0]=f2tf(br[l].x); d[1]=f2tf(br[l].y); d[2]=f2tf(br[l].z); d[3]=f2tf(br[l].w); } } }

    LDA_Z(0); LDB_Z(0);
    STA_G(0); STB_G(0);
    LDA_Z(16); LDB_Z(16);
    __syncthreads();

    for (int it = 0; it < 12; it++) {
        const int st = it & 1;
        if (it < 11) { STA_G(st ^ 1); STB_G(st ^ 1); }
        if (it < 10) { LDA_Z(16 * (it + 2)); LDB_Z(16 * (it + 2)); }

        const unsigned* Bsl = Bs[st];
        const uint32_t aBase = sAs + (uint32_t)(st * 3840 * 4) + aoff;
#pragma unroll
        for (int h = 0; h < 2; h++) {
            const int kk = h * 8;
            unsigned af[3][4], bf[6][2];
#pragma unroll
            for (int mt = 0; mt < 3; mt++) {
                const int r0 = wm * 48 + mt * 16;
                ldsm_x4(af[mt], aBase + (uint32_t)((r0 * 20 + kk) * 4));
            }
#pragma unroll
            for (int nt = 0; nt < 6; nt++) {
                const int col = wn * 48 + nt * 8 + gid;
                bf[nt][0] = Bsl[(kk + tid4) * 104 + col];
                bf[nt][1] = Bsl[(kk + tid4 + 4) * 104 + col];
            }
#pragma unroll
            for (int mt = 0; mt < 3; mt++)
#pragma unroll
                for (int nt = 0; nt < 6; nt++)
                    mma_tf32(acc[mt][nt], af[mt], bf[nt]);
        }
        __syncthreads();
    }

#pragma unroll
    for (int mt = 0; mt < 3; mt++) {
        const int r0 = wm * 48 + mt * 16 + gid;
#pragma unroll
        for (int nt = 0; nt < 6; nt++) {
            const int col = wn * 48 + nt * 8 + 2 * tid4;
            *(float2*)(zb + (size_t)r0 * NVOX + col) = make_float2(acc[mt][nt][0], acc[mt][nt][1]);
            *(float2*)(zb + (size_t)(r0 + 8) * NVOX + col) = make_float2(acc[mt][nt][2], acc[mt][nt][3]);
        }
    }
}

// ---------------------------------------------------------------------------
// K3: score partials v2. grid (12, H, B), 256 thr.
// ---------------------------------------------------------------------------
__global__ __launch_bounds__(256) void scores_kernel(const float* __restrict__ x)
{
    __shared__ float Xq[2][32][36], Zq[2][32][36], Xk[2][32][36], Zk[2][32][36];
    __shared__ float wbs[32];
    __shared__ float Sh[2][32][32];

    const int isl = blockIdx.x >> 1, ep = blockIdx.x & 1;
    const int h = blockIdx.y, b = blockIdx.z;
    const int i0 = isl * 32, e0 = ep * 12;
    const int t = threadIdx.x;
    const int wid = t >> 5, lane = t & 31;
    const int h32 = h * 32;

    const float* xb = x + (size_t)b * CH * NVOX;
    const float* zb = g_Z + (size_t)b * CH * NVOX;

    if (t < 32) wbs[t] = g_wb[i0 + t];

    const int li  = t >> 3;
    const int lc4 = (t & 7) << 2;

    const int ihalf = wid >> 1;
    const int sig = (wid & 1) * 32 + lane;
    const int ccg = sig >> 3;
    const int d0c = (sig & 7) << 2;

    float s[4][4];
#pragma unroll
    for (int a = 0; a < 4; a++)
#pragma unroll
        for (int q = 0; q < 4; q++) s[a][q] = 0.f;
    float dac = 0.f, wac = 0.f;

    const size_t rowoff = (size_t)(i0 + li) * NVOX;
    float4 rq, rzq, rk, rzk;
    {
        const int u = 576 * e0 + h32 + lc4;
        rq  = *(const float4*)(xb + rowoff + u);
        rzq = *(const float4*)(zb + rowoff + u);
        rk  = *(const float4*)(xb + rowoff + u + 192);
        rzk = *(const float4*)(zb + rowoff + u + 192);
    }
    *(float4*)&Xq[0][li][lc4] = rq;  *(float4*)&Zq[0][li][lc4] = rzq;
    *(float4*)&Xk[0][li][lc4] = rk;  *(float4*)&Zk[0][li][lc4] = rzk;
    __syncthreads();

    for (int e = 0; e < 12; e++) {
        const int cur = e & 1, nxt = cur ^ 1;
        if (e < 11) {
            const int u = 576 * (e0 + e + 1) + h32 + lc4;
            rq  = *(const float4*)(xb + rowoff + u);
            rzq = *(const float4*)(zb + rowoff + u);
            rk  = *(const float4*)(xb + rowoff + u + 192);
            rzk = *(const float4*)(zb + rowoff + u + 192);
        }
        if (wid < 4) {
            const int ib = ihalf * 16;
#pragma unroll
            for (int ii = 0; ii < 16; ii++) {
                const int i = ib + ii;
                const float4 zv = *(const float4*)&Zk[cur][i][d0c];
                const float q0 = Xq[cur][i][ccg];
                const float q1 = Xq[cur][i][ccg + 8];
                const float q2 = Xq[cur][i][ccg + 16];
                const float q3 = Xq[cur][i][ccg + 24];
                s[0][0] += q0 * zv.x; s[0][1] += q0 * zv.y; s[0][2] += q0 * zv.z; s[0][3] += q0 * zv.w;
                s[1][0] += q1 * zv.x; s[1][1] += q1 * zv.y; s[1][2] += q1 * zv.z; s[1][3] += q1 * zv.w;
                s[2][0] += q2 * zv.x; s[2][1] += q2 * zv.y; s[2][2] += q2 * zv.z; s[2][3] += q2 * zv.w;
                s[3][0] += q3 * zv.x; s[3][1] += q3 * zv.y; s[3][2] += q3 * zv.z; s[3][3] += q3 * zv.w;
            }
        } else if (wid == 4) {
#pragma unroll
            for (int i = 0; i < 32; i++) {
                const float xv = Xq[cur][i][lane];
                dac += xv * Zq[cur][i][lane];
                wac += wbs[i] * xv;
            }
        } else if (wid == 5) {
#pragma unroll
            for (int i = 0; i < 32; i++) {
                const float xv = Xk[cur][i][lane];
                dac += xv * Zk[cur][i][lane];
                wac += wbs[i] * xv;
            }
        }
        if (e < 11) {
            *(float4*)&Xq[nxt][li][lc4] = rq;  *(float4*)&Zq[nxt][li][lc4] = rzq;
            *(float4*)&Xk[nxt][li][lc4] = rk;  *(float4*)&Zk[nxt][li][lc4] = rzk;
        }
        __syncthreads();
    }

    if (wid < 4) {
#pragma unroll
        for (int a = 0; a < 4; a++)
            *(float4*)&Sh[ihalf][ccg + 8 * a][d0c] =
                make_float4(s[a][0], s[a][1], s[a][2], s[a][3]);
    }
    __syncthreads();

    float* sp = g_spart + (size_t)((b * HEADS + h) * 12 + blockIdx.x) * 1152;
    {
        const int eidx = t * 4;
        const float* s0 = &Sh[0][0][0];
        const float* s1 = &Sh[1][0][0];
        float4 a = *(const float4*)(s0 + eidx);
        float4 c = *(const float4*)(s1 + eidx);
        sp[eidx + 0] = a.x + c.x;
        sp[eidx + 1] = a.y + c.y;
        sp[eidx + 2] = a.z + c.z;
        sp[eidx + 3] = a.w + c.w;
    }
    if (wid == 4) { sp[1024 + lane] = dac; sp[1088 + lane] = wac; }
    if (wid == 5) { sp[1056 + lane] = dac; sp[1120 + lane] = wac; }
}

// ---------------------------------------------------------------------------
// K4 (fused, split): grid (HEADS, BATCH, 2). Each block: full softmax (cheap,
// redundant across z) + mmix over its 96-o half. pwr prefetched at entry.
// ---------------------------------------------------------------------------
__global__ __launch_bounds__(256) void softmax_mmix_kernel(const float* __restrict__ temp)
{
    __shared__ float sS[1024];
    __shared__ float snq[32], snk[32], swq[32], swk[32];
    __shared__ float att[32][32];

    const int h = blockIdx.x, b = blockIdx.y;
    const int oh = blockIdx.z;             // o half: 0 or 1
    const int t = threadIdx.x;
    const float b2 = g_c[0];
    const float* sp = g_spart + (size_t)((b * HEADS + h) * 12) * 1152;

    // Prefetch mmix weights early (independent of softmax).
    const int o = oh * 96 + (t < 96 ? t : 0);
    float pwr[32];
    if (t < 96) {
#pragma unroll
        for (int cc = 0; cc < 32; cc++)
            pwr[cc] = g_pwT[(cc * HEADS + h) * CH + o];
    }

    // Partial reduction: fully unrolled so all loads batch.
    {
        float a0 = 0.f, a1 = 0.f, a2 = 0.f, a3 = 0.f;
#pragma unroll
        for (int s = 0; s < 12; s++) {
            a0 += sp[s * 1152 + t];
            a1 += sp[s * 1152 + t + 256];
            a2 += sp[s * 1152 + t + 512];
            a3 += sp[s * 1152 + t + 768];
        }
        sS[t] = a0; sS[t + 256] = a1; sS[t + 512] = a2; sS[t + 768] = a3;
    }
    if (t < 64) {
        float d = 0.f, wv = 0.f;
        const int od = 1024 + t, ow = 1088 + t;
#pragma unroll
        for (int s = 0; s < 12; s++) { d += sp[s * 1152 + od]; wv += sp[s * 1152 + ow]; }
        const float n2 = d + 2.f * wv + 24.f * b2;
        const float r = fmaxf(sqrtf(fmaxf(n2, 0.f)), EPSN);
        if (t < 32) { snq[t] = r; swq[t] = wv; }
        else        { snk[t - 32] = r; swk[t - 32] = wv; }
    }
    __syncthreads();

    const int w = t >> 5, lane = t & 31;
    const float tv = temp[h];

    for (int r = 0; r < 4; r++) {
        const int c = w * 4 + r;
        const float Sfull = sS[c * 32 + lane] + swq[c] + swk[lane] + 24.f * b2;
        float L = Sfull / (snq[c] * snk[lane]) * tv;
        float mx = L;
#pragma unroll
        for (int oo = 16; oo > 0; oo >>= 1) mx = fmaxf(mx, __shfl_xor_sync(0xffffffffu, mx, oo));
        const float ev = expf(L - mx);
        float sm = ev;
#pragma unroll
        for (int oo = 16; oo > 0; oo >>= 1) sm += __shfl_xor_sync(0xffffffffu, sm, oo);
        att[c][lane] = ev / sm;
    }
    __syncthreads();

    // mmix: M[b][o][h*32+d] = sum_cc pwr[cc] * att[cc][d]
    if (t < 96) {
        float s[32];
#pragma unroll
        for (int d = 0; d < 32; d++) s[d] = 0.f;
#pragma unroll 8
        for (int cc = 0; cc < 32; cc++) {
            const float v = pwr[cc];
#pragma unroll
            for (int d4 = 0; d4 < 8; d4++) {
                const float4 a = *(const float4*)&att[cc][d4 * 4];
                s[d4 * 4 + 0] += v * a.x;
                s[d4 * 4 + 1] += v * a.y;
                s[d4 * 4 + 2] += v * a.z;
                s[d4 * 4 + 3] += v * a.w;
            }
        }
        float* Mb = g_M + (size_t)b * CH * CH + (size_t)o * CH + h * HD;
#pragma unroll
        for (int d = 0; d < 32; d++) Mb[d] = s[d];
    }
}

// ---------------------------------------------------------------------------
// K6a (t_gemm): T[b][o][e*192+c] = sum_k M[o,k] * X[c, 576e+384+k]
// BM=96 (c rows, split by blockIdx.y), BN=96 (o cols), K=192.
// 8 warps = 2m x 4n, warp tile 48x24 (3x3). grid (48, 2, 8).
// ---------------------------------------------------------------------------
__global__ __launch_bounds__(256, 2) void t_gemm(const float* __restrict__ x)
{
    __shared__ unsigned As[2][96 * 20];
    __shared__ unsigned Bs[2][96 * 20];

    const int b  = blockIdx.z;
    const int e  = blockIdx.x >> 1;
    const int oB = (blockIdx.x & 1) * 96;
    const int ch = blockIdx.y;           // c half: 0 or 1
    const int t  = threadIdx.x;
    const int wid = t >> 5, lane = t & 31;
    const int wm = wid & 1, wn = wid >> 1;   // 2m x 4n
    const int gid = lane >> 2, tid4 = lane & 3;

    const float* Asrc = x + (size_t)b * CH * NVOX + (size_t)(ch * 96) * NVOX + 576 * e + 384;
    const float* Bsrc = g_M + (size_t)b * CH * CH + (size_t)oB * CH;
    float* Tb = g_V + (size_t)b * TSTRIDE;

    const uint32_t sAs = smem_u32(As);
    const uint32_t sBs = smem_u32(Bs);
    const uint32_t aoff = (uint32_t)((((lane & 7) + ((lane >> 3) & 1) * 8) * 20 +
                                      ((lane >> 4) * 4)) * 4);
    const uint32_t boff = (uint32_t)(((lane & 7) * 20 + ((lane >> 3) & 1) * 4) * 4);

    float acc[3][3][4];
#pragma unroll
    for (int i = 0; i < 3; i++)
#pragma unroll
        for (int q = 0; q < 3; q++)
#pragma unroll
            for (int r = 0; r < 4; r++) acc[i][q][r] = 0.f;

    float4 ar[2], br[2];
#define LDA_T2(K0) { _Pragma("unroll") for (int l = 0; l < 2; l++) {                     \
                       const int idx = l * 256 + t;                                      \
                       if (idx < 384)                                                    \
                         ar[l] = *(const float4*)(Asrc + (size_t)(idx >> 2) * NVOX + (K0) + (idx & 3) * 4); } }
#define LDB_T2(K0) { _Pragma("unroll") for (int l = 0; l < 2; l++) {                     \
                       const int idx = l * 256 + t;                                      \
                       if (idx < 384)                                                    \
                         br[l] = *(const float4*)(Bsrc + (size_t)(idx >> 2) * CH + (K0) + (idx & 3) * 4); } }
#define STA_T2(ST) { _Pragma("unroll") for (int l = 0; l < 2; l++) {                     \
                       const int idx = l * 256 + t;                                      \
                       if (idx < 384) {                                                  \
                         unsigned* d = &As[ST][(idx >> 2) * 20 + (idx & 3) * 4];         \
                         d[0]=f2tf(ar[l].x); d[1]=f2tf(ar[l].y); d[2]=f2tf(ar[l].z); d[3]=f2tf(ar[l].w); } } }
#define STB_T2(ST) { _Pragma("unroll") for (int l = 0; l < 2; l++) {                     \
                       const int idx = l * 256 + t;                                      \
                       if (idx < 384) {                                                  \
                         unsigned* d = &Bs[ST][(idx >> 2) * 20 + (idx & 3) * 4];         \
                         d[0]=f2tf(br[l].x); d[1]=f2tf(br[l].y); d[2]=f2tf(br[l].z); d[3]=f2tf(br[l].w); } } }

    LDA_T2(0); LDB_T2(0);
    STA_T2(0); STB_T2(0);
    LDA_T2(16); LDB_T2(16);
    __syncthreads();

    for (int it = 0; it < 12; it++) {
        const int st = it & 1;
        if (it < 11) { STA_T2(st ^ 1); STB_T2(st ^ 1); }
        if (it < 10) { LDA_T2(16 * (it + 2)); LDB_T2(16 * (it + 2)); }

        const uint32_t aBase = sAs + (uint32_t)(st * 1920 * 4) + aoff;
        const uint32_t bBase = sBs + (uint32_t)(st * 1920 * 4) + boff;
#pragma unroll
        for (int h = 0; h < 2; h++) {
            const int kk = h * 8;
            unsigned af[3][4], bf[3][2];
#pragma unroll
            for (int mt = 0; mt < 3; mt++) {
                const int r0 = wm * 48 + mt * 16;
                ldsm_x4(af[mt], aBase + (uint32_t)((r0 * 20 + kk) * 4));
            }
#pragma unroll
            for (int nt = 0; nt < 3; nt++) {
                const int c0 = wn * 24 + nt * 8;
                ldsm_x2(bf[nt], bBase + (uint32_t)((c0 * 20 + kk) * 4));
            }
#pragma unroll
            for (int mt = 0; mt < 3; mt++)
#pragma unroll
                for (int nt = 0; nt < 3; nt++)
                    mma_tf32(acc[mt][nt], af[mt], bf[nt]);
        }
        __syncthreads();
    }

#pragma unroll
    for (int mt = 0; mt < 3; mt++) {
        const int c0 = ch * 96 + wm * 48 + mt * 16 + gid;
#pragma unroll
        for (int nt = 0; nt < 3; nt++) {
            const int o0 = oB + wn * 24 + nt * 8 + 2 * tid4;
            float* p0 = Tb + (size_t)o0 * 4608 + e * 192;
            float* p1 = Tb + (size_t)(o0 + 1) * 4608 + e * 192;
            p0[c0]     = acc[mt][nt][0];
            p1[c0]     = acc[mt][nt][1];
            p0[c0 + 8] = acc[mt][nt][2];
            p1[c0 + 8] = acc[mt][nt][3];
        }
    }
}

// ---------------------------------------------------------------------------
// K6b (y_gemm): y[o][24a+e] = sum_c W[a,c]*T[o][e*192+c] + msum[o]*beta[a] + pbias[o]
// BM=192, BN=96 (4 o x 24 e), K=192. grid (48, 3, 8).
// ---------------------------------------------------------------------------
__global__ __launch_bounds__(256, 2) void y_gemm(float* __restrict__ y,
                                                 const float* __restrict__ qkv_w,
                                                 const float* __restrict__ qkv_b,
                                                 const float* __restrict__ pbias)
{
    __shared__ unsigned As[2][192 * 20];
    __shared__ unsigned Bs[2][96 * 20];

    const int b  = blockIdx.z;
    const int m0 = blockIdx.y * 192;
    const int cb = blockIdx.x;           // 0..47 -> o base = cb*4
    const int t  = threadIdx.x;
    const int wid = t >> 5, lane = t & 31;
    const int wm = wid & 3, wn = wid >> 2;
    const int gid = lane >> 2, tid4 = lane & 3;

    const float* Asrc = qkv_w + (size_t)m0 * CH;
    const float* Tb = g_V + (size_t)b * TSTRIDE + (size_t)cb * 4 * 4608;
    float* yb = y + (size_t)b * CH * NVOX;

    const uint32_t sAs = smem_u32(As);
    const uint32_t sBs = smem_u32(Bs);
    const uint32_t aoff = (uint32_t)((((lane & 7) + ((lane >> 3) & 1) * 8) * 20 +
                                      ((lane >> 4) * 4)) * 4);
    const uint32_t boff = (uint32_t)(((lane & 7) * 20 + ((lane >> 3) & 1) * 4) * 4);

    float acc[3][6][4];
#pragma unroll
    for (int i = 0; i < 3; i++)
#pragma unroll
        for (int q = 0; q < 6; q++)
#pragma unroll
            for (int r = 0; r < 4; r++) acc[i][q][r] = 0.f;

    float4 ar[3], br[2];
#define LDA_Y(K0) { _Pragma("unroll") for (int l = 0; l < 3; l++) {                      \
                      const int idx = l * 256 + t;                                       \
                      ar[l] = *(const float4*)(Asrc + (size_t)(idx >> 2) * CH + (K0) + (idx & 3) * 4); } }
#define LDB_Y(K0) { _Pragma("unroll") for (int l = 0; l < 2; l++) {                      \
                      const int idx = l * 256 + t;                                       \
                      if (idx < 384) {                                                   \
                        const int jj = idx >> 2;                                         \
                        br[l] = *(const float4*)(Tb + (size_t)(jj / 24) * 4608 +         \
                                                 (jj % 24) * 192 + (K0) + (idx & 3) * 4); } } }
#define STA_Y(ST) { _Pragma("unroll") for (int l = 0; l < 3; l++) {                      \
                      const int idx = l * 256 + t;                                       \
                      unsigned* d = &As[ST][(idx >> 2) * 20 + (idx & 3) * 4];            \
                      d[0]=f2tf(ar[l].x); d[1]=f2tf(ar[l].y); d[2]=f2tf(ar[l].z); d[3]=f2tf(ar[l].w); } }
#define STB_Y(ST) { _Pragma("unroll") for (int l = 0; l < 2; l++) {                      \
                      const int idx = l * 256 + t;                                       \
                      if (idx < 384) {                                                   \
                        unsigned* d = &Bs[ST][(idx >> 2) * 20 + (idx & 3) * 4];          \
                        d[0]=f2tf(br[l].x); d[1]=f2tf(br[l].y); d[2]=f2tf(br[l].z); d[3]=f2tf(br[l].w); } } }

    LDA_Y(0); LDB_Y(0);
    STA_Y(0); STB_Y(0);
    LDA_Y(16); LDB_Y(16);
    __syncthreads();

    for (int it = 0; it < 12; it++) {
        const int st = it & 1;
        if (it < 11) { STA_Y(st ^ 1); STB_Y(st ^ 1); }
        if (it < 10) { LDA_Y(16 * (it + 2)); LDB_Y(16 * (it + 2)); }

        const uint32_t aBase = sAs + (uint32_t)(st * 3840 * 4) + aoff;
        const uint32_t bBase = sBs + (uint32_t)(st * 1920 * 4) + boff;
#pragma unroll
        for (int h = 0; h < 2; h++) {
            const int kk = h * 8;
            unsigned af[3][4], bf[6][2];
#pragma unroll
            for (int mt = 0; mt < 3; mt++) {
                const int r0 = wm * 48 + mt * 16;
                ldsm_x4(af[mt], aBase + (uint32_t)((r0 * 20 + kk) * 4));
            }
#pragma unroll
            for (int nt = 0; nt < 6; nt++) {
                const int c0 = wn * 48 + nt * 8;
                ldsm_x2(bf[nt], bBase + (uint32_t)((c0 * 20 + kk) * 4));
            }
#pragma unroll
            for (int mt = 0; mt < 3; mt++)
#pragma unroll
                for (int nt = 0; nt < 6; nt++)
                    mma_tf32(acc[mt][nt], af[mt], bf[nt]);
        }
        __syncthreads();
    }

#pragma unroll
    for (int mt = 0; mt < 3; mt++) {
        const int r0 = wm * 48 + mt * 16 + gid;
        const int a0 = m0 + r0;
        const float be0 = qkv_b[a0], be1 = qkv_b[a0 + 8];
#pragma unroll
        for (int nt = 0; nt < 6; nt++) {
            const int j0 = wn * 48 + nt * 8 + 2 * tid4;
            const int o  = cb * 4 + j0 / 24;
            const int e  = j0 % 24;
            const float ms = g_msum[o];
            const float pb = pbias[o];
            const float bias0 = ms * be0 + pb;
            const float bias1 = ms * be1 + pb;
            *(float2*)(yb + (size_t)o * NVOX + 24 * a0 + e) =
                make_float2(acc[mt][nt][0] + bias0, acc[mt][nt][1] + bias0);
            *(float2*)(yb + (size_t)o * NVOX + 24 * (a0 + 8) + e) =
                make_float2(acc[mt][nt][2] + bias1, acc[mt][nt][3] + bias1);
        }
    }
}

// ---------------------------------------------------------------------------
extern "C" void kernel_launch(void* const* d_in, const int* in_sizes, int n_in,
                              void* d_out, int out_size)
{
    const float* x      = (const float*)d_in[0];
    const float* qkv_w  = (const float*)d_in[1];
    const float* qkv_b  = (const float*)d_in[2];
    const float* temp   = (const float*)d_in[3];
    const float* proj_w = (const float*)d_in[4];
    const float* proj_b = (const float*)d_in[5];
    float* y = (float*)d_out;

    pre_kernel         <<<73, 256>>>(qkv_w, qkv_b, proj_w);
    z_gemm             <<<dim3(96, 1, BATCH), 256>>>(x);
    scores_kernel      <<<dim3(12, HEADS, BATCH), 256>>>(x);
    softmax_mmix_kernel<<<dim3(HEADS, BATCH, 2), 256>>>(temp);
    t_gemm             <<<dim3(48, 2, BATCH), 256>>>(x);
    y_gemm             <<<dim3(48, 3, BATCH), 256>>>(y, qkv_w, qkv_b, proj_b);
}

// round 17
// speedup vs baseline: 1.0568x; 1.0074x over previous
#include <cuda_runtime.h>
#include <cuda_bf16.h>
#include <math.h>
#include <stdint.h>

#define BATCH  8
#define CH     192
#define C3     576
#define NVOX   13824       // 24*24*24
#define HEADS  6
#define HD     32
#define EPSN   1e-12f
#define TSTRIDE (CH * 4608)

// Scratch
__device__ __nv_bfloat16 g_Zh[(size_t)BATCH * CH * NVOX];  // Z in bf16 (43 MB)
__device__ float g_V[(size_t)BATCH * NVOX * CH];           // T[b][o][e*192+c]
__device__ float g_Gw[CH * CH];
__device__ float g_wb[CH];
__device__ float g_pwT[CH * CH];
__device__ float g_msum[CH];
__device__ float g_c[4];                                   // [0] = b2
__device__ float g_spart[BATCH * HEADS * 12 * 1152];
__device__ float g_M[BATCH * CH * CH];

// ---------------------------------------------------------------------------
__device__ __forceinline__ unsigned f2tf(float f) {
    unsigned u;
    asm("cvt.rna.tf32.f32 %0, %1;" : "=r"(u) : "f"(f));
    return u;
}
__device__ __forceinline__ void mma_tf32(float* c, const unsigned* a, const unsigned* b) {
    asm volatile(
        "mma.sync.aligned.m16n8k8.row.col.f32.tf32.tf32.f32 "
        "{%0,%1,%2,%3},{%4,%5,%6,%7},{%8,%9},{%0,%1,%2,%3};"
        : "+f"(c[0]), "+f"(c[1]), "+f"(c[2]), "+f"(c[3])
        : "r"(a[0]), "r"(a[1]), "r"(a[2]), "r"(a[3]), "r"(b[0]), "r"(b[1]));
}
__device__ __forceinline__ uint32_t smem_u32(const void* p) {
    uint32_t a;
    asm("{ .reg .u64 t; cvta.to.shared.u64 t, %1; cvt.u32.u64 %0, t; }" : "=r"(a) : "l"(p));
    return a;
}
__device__ __forceinline__ void ldsm_x4(unsigned* r, uint32_t addr) {
    asm volatile("ldmatrix.sync.aligned.m8n8.x4.shared.b16 {%0,%1,%2,%3}, [%4];"
        : "=r"(r[0]), "=r"(r[1]), "=r"(r[2]), "=r"(r[3]) : "r"(addr));
}
__device__ __forceinline__ void ldsm_x2(unsigned* r, uint32_t addr) {
    asm volatile("ldmatrix.sync.aligned.m8n8.x2.shared.b16 {%0,%1}, [%2];"
        : "=r"(r[0]), "=r"(r[1]) : "r"(addr));
}

// ---------------------------------------------------------------------------
// K0 merged prekernel: blocks 0..35 Gw tiles; 36..71 pwT tiles; 72 wb+b2+msum.
// ---------------------------------------------------------------------------
__global__ __launch_bounds__(256) void pre_kernel(const float* __restrict__ w,
                                                  const float* __restrict__ beta,
                                                  const float* __restrict__ pw)
{
    __shared__ float sh[2112];
    const int bid = blockIdx.x;
    const int t = threadIdx.x;

    if (bid < 36) {
        float (*Wi)[33] = (float (*)[33])sh;
        float (*Wj)[33] = (float (*)[33])(sh + 1056);
        const int i0 = (bid % 6) * 32, j0 = (bid / 6) * 32;
        const int ti = t & 31, tj = (t >> 5) * 4;
        float acc[4] = {0.f, 0.f, 0.f, 0.f};
        for (int a0 = 0; a0 < C3; a0 += 32) {
            __syncthreads();
#pragma unroll
            for (int l = 0; l < 4; l++) {
                const int a = (t >> 5) + 8 * l, c = t & 31;
                Wi[a][c] = w[(a0 + a) * CH + i0 + c];
                Wj[a][c] = w[(a0 + a) * CH + j0 + c];
            }
            __syncthreads();
#pragma unroll
            for (int a = 0; a < 32; a++) {
                const float wi = Wi[a][ti];
#pragma unroll
                for (int r = 0; r < 4; r++) acc[r] += wi * Wj[a][tj + r];
            }
        }
#pragma unroll
        for (int r = 0; r < 4; r++) g_Gw[(i0 + ti) * CH + j0 + tj + r] = acc[r];
    } else if (bid < 72) {
        float (*tile)[33] = (float (*)[33])sh;
        const int bb = bid - 36;
        const int bx = (bb % 6) * 32, by = (bb / 6) * 32;
        const int tx = t & 31, ty = t >> 5;
#pragma unroll
        for (int l = 0; l < 4; l++)
            tile[ty + 8 * l][tx] = pw[(by + ty + 8 * l) * CH + bx + tx];
        __syncthreads();
#pragma unroll
        for (int l = 0; l < 4; l++)
            g_pwT[(bx + ty + 8 * l) * CH + by + tx] = tile[tx][ty + 8 * l];
    } else {
        if (t < CH) {
            float s = 0.f;
            for (int a = 0; a < C3; a++) s += beta[a] * w[a * CH + t];
            g_wb[t] = s;
            float ms = 0.f;
#pragma unroll 4
            for (int c = 0; c < CH; c += 4) {
                const float4 v = *(const float4*)(pw + (size_t)t * CH + c);
                ms += v.x + v.y + v.z + v.w;
            }
            g_msum[t] = ms;
        }
        if (t < 64) {
            float p = 0.f;
            for (int a = t; a < C3; a += 64) p += beta[a] * beta[a];
            sh[t] = p;
        }
        __syncthreads();
        if (t == 0) {
            float s = 0.f;
            for (int i = 0; i < 64; i++) s += sh[i];
            g_c[0] = s;
        }
    }
}

// ---------------------------------------------------------------------------
// K1: Z[b] = Gw @ X[b] (bf16 output), columns 576e + 96j, j<4.
// BM=192, BN=96, BK=16, 256 thr, warp 48x48, 2 CTA/SM.
// ---------------------------------------------------------------------------
__global__ __launch_bounds__(256, 2) void z_gemm(const float* __restrict__ x)
{
    __shared__ unsigned As[2][192 * 20];
    __shared__ unsigned Bs[2][16 * 104];

    const int b = blockIdx.z;
    const int e = blockIdx.x >> 2, j = blockIdx.x & 3;
    const int n0 = 576 * e + 96 * j;
    const int t = threadIdx.x;
    const int wid = t >> 5, lane = t & 31;
    const int wm = wid & 3, wn = wid >> 2;
    const int gid = lane >> 2, tid4 = lane & 3;

    const float* bsrc = x + (size_t)b * CH * NVOX + n0;
    __nv_bfloat16* zb = g_Zh + (size_t)b * CH * NVOX + n0;

    const uint32_t sAs = smem_u32(As);
    const uint32_t aoff = (uint32_t)((((lane & 7) + ((lane >> 3) & 1) * 8) * 20 +
                                      ((lane >> 4) * 4)) * 4);

    float acc[3][6][4];
#pragma unroll
    for (int i = 0; i < 3; i++)
#pragma unroll
        for (int q = 0; q < 6; q++)
#pragma unroll
            for (int r = 0; r < 4; r++) acc[i][q][r] = 0.f;

    float4 ar[3], br[2];
#define LDA_Z(K0) { _Pragma("unroll") for (int l = 0; l < 3; l++) {                      \
                      const int idx = l * 256 + t;                                       \
                      ar[l] = *(const float4*)(g_Gw + (idx >> 2) * CH + (K0) + (idx & 3) * 4); } }
#define LDB_Z(K0) { _Pragma("unroll") for (int l = 0; l < 2; l++) {                      \
                      const int idx = l * 256 + t;                                       \
                      if (idx < 384)                                                     \
                        br[l] = *(const float4*)(bsrc + (size_t)((K0) + idx / 24) * NVOX + (idx % 24) * 4); } }
#define STA_G(ST) { _Pragma("unroll") for (int l = 0; l < 3; l++) {                      \
                      const int idx = l * 256 + t;                                       \
                      unsigned* d = &As[ST][(idx >> 2) * 20 + (idx & 3) * 4];            \
                      d[0]=f2tf(ar[l].x); d[1]=f2tf(ar[l].y); d[2]=f2tf(ar[l].z); d[3]=f2tf(ar[l].w); } }
#define STB_G(ST) { _Pragma("unroll") for (int l = 0; l < 2; l++) {                      \
                      const int idx = l * 256 + t;                                       \
                      if (idx < 384) {                                                   \
                        unsigned* d = &Bs[ST][(idx / 24) * 104 + (idx % 24) * 4];        \
                        d[0]=f2tf(br[l].x); d[1]=f2tf(br[l].y); d[2]=f2tf(br[l].z); d[3]=f2tf(br[l].w); } } }

    LDA_Z(0); LDB_Z(0);
    STA_G(0); STB_G(0);
    LDA_Z(16); LDB_Z(16);
    __syncthreads();

    for (int it = 0; it < 12; it++) {
        const int st = it & 1;
        if (it < 11) { STA_G(st ^ 1); STB_G(st ^ 1); }
        if (it < 10) { LDA_Z(16 * (it + 2)); LDB_Z(16 * (it + 2)); }

        const unsigned* Bsl = Bs[st];
        const uint32_t aBase = sAs + (uint32_t)(st * 3840 * 4) + aoff;
#pragma unroll
        for (int h = 0; h < 2; h++) {
            const int kk = h * 8;
            unsigned af[3][4], bf[6][2];
#pragma unroll
            for (int mt = 0; mt < 3; mt++) {
                const int r0 = wm * 48 + mt * 16;
                ldsm_x4(af[mt], aBase + (uint32_t)((r0 * 20 + kk) * 4));
            }
#pragma unroll
            for (int nt = 0; nt < 6; nt++) {
                const int col = wn * 48 + nt * 8 + gid;
                bf[nt][0] = Bsl[(kk + tid4) * 104 + col];
                bf[nt][1] = Bsl[(kk + tid4 + 4) * 104 + col];
            }
#pragma unroll
            for (int mt = 0; mt < 3; mt++)
#pragma unroll
                for (int nt = 0; nt < 6; nt++)
                    mma_tf32(acc[mt][nt], af[mt], bf[nt]);
        }
        __syncthreads();
    }

#pragma unroll
    for (int mt = 0; mt < 3; mt++) {
        const int r0 = wm * 48 + mt * 16 + gid;
#pragma unroll
        for (int nt = 0; nt < 6; nt++) {
            const int col = wn * 48 + nt * 8 + 2 * tid4;
            *(__nv_bfloat162*)(zb + (size_t)r0 * NVOX + col) =
                __floats2bfloat162_rn(acc[mt][nt][0], acc[mt][nt][1]);
            *(__nv_bfloat162*)(zb + (size_t)(r0 + 8) * NVOX + col) =
                __floats2bfloat162_rn(acc[mt][nt][2], acc[mt][nt][3]);
        }
    }
}

// ---------------------------------------------------------------------------
// K3: score partials v2 (Z in bf16). grid (12, H, B), 256 thr.
// ---------------------------------------------------------------------------
__global__ __launch_bounds__(256) void scores_kernel(const float* __restrict__ x)
{
    __shared__ float Xq[2][32][36], Zq[2][32][36], Xk[2][32][36], Zk[2][32][36];
    __shared__ float wbs[32];
    __shared__ float Sh[2][32][32];

    const int isl = blockIdx.x >> 1, ep = blockIdx.x & 1;
    const int h = blockIdx.y, b = blockIdx.z;
    const int i0 = isl * 32, e0 = ep * 12;
    const int t = threadIdx.x;
    const int wid = t >> 5, lane = t & 31;
    const int h32 = h * 32;

    const float* xb = x + (size_t)b * CH * NVOX;
    const __nv_bfloat16* zb = g_Zh + (size_t)b * CH * NVOX;

    if (t < 32) wbs[t] = g_wb[i0 + t];

    const int li  = t >> 3;
    const int lc4 = (t & 7) << 2;

    const int ihalf = wid >> 1;
    const int sig = (wid & 1) * 32 + lane;
    const int ccg = sig >> 3;
    const int d0c = (sig & 7) << 2;

    float s[4][4];
#pragma unroll
    for (int a = 0; a < 4; a++)
#pragma unroll
        for (int q = 0; q < 4; q++) s[a][q] = 0.f;
    float dac = 0.f, wac = 0.f;

    const size_t rowoff = (size_t)(i0 + li) * NVOX;
    float4 rq, rk;
    uint2 rzq, rzk;
#define SC_LD(E) { const int u = 576 * (E) + h32 + lc4;                      \
                   rq  = *(const float4*)(xb + rowoff + u);                  \
                   rzq = *(const uint2*)(zb + rowoff + u);                   \
                   rk  = *(const float4*)(xb + rowoff + u + 192);            \
                   rzk = *(const uint2*)(zb + rowoff + u + 192); }
#define SC_ST(BUF) { *(float4*)&Xq[BUF][li][lc4] = rq;                                          \
                     *(float4*)&Xk[BUF][li][lc4] = rk;                                          \
                     { float2 f0 = __bfloat1622float2(*(__nv_bfloat162*)&rzq.x);                \
                       float2 f1 = __bfloat1622float2(*(__nv_bfloat162*)&rzq.y);                \
                       *(float4*)&Zq[BUF][li][lc4] = make_float4(f0.x, f0.y, f1.x, f1.y); }     \
                     { float2 f0 = __bfloat1622float2(*(__nv_bfloat162*)&rzk.x);                \
                       float2 f1 = __bfloat1622float2(*(__nv_bfloat162*)&rzk.y);                \
                       *(float4*)&Zk[BUF][li][lc4] = make_float4(f0.x, f0.y, f1.x, f1.y); } }

    SC_LD(e0);
    SC_ST(0);
    __syncthreads();

    for (int e = 0; e < 12; e++) {
        const int cur = e & 1, nxt = cur ^ 1;
        if (e < 11) { SC_LD(e0 + e + 1); }
        if (wid < 4) {
            const int ib = ihalf * 16;
#pragma unroll
            for (int ii = 0; ii < 16; ii++) {
                const int i = ib + ii;
                const float4 zv = *(const float4*)&Zk[cur][i][d0c];
                const float q0 = Xq[cur][i][ccg];
                const float q1 = Xq[cur][i][ccg + 8];
                const float q2 = Xq[cur][i][ccg + 16];
                const float q3 = Xq[cur][i][ccg + 24];
                s[0][0] += q0 * zv.x; s[0][1] += q0 * zv.y; s[0][2] += q0 * zv.z; s[0][3] += q0 * zv.w;
                s[1][0] += q1 * zv.x; s[1][1] += q1 * zv.y; s[1][2] += q1 * zv.z; s[1][3] += q1 * zv.w;
                s[2][0] += q2 * zv.x; s[2][1] += q2 * zv.y; s[2][2] += q2 * zv.z; s[2][3] += q2 * zv.w;
                s[3][0] += q3 * zv.x; s[3][1] += q3 * zv.y; s[3][2] += q3 * zv.z; s[3][3] += q3 * zv.w;
            }
        } else if (wid == 4) {
#pragma unroll
            for (int i = 0; i < 32; i++) {
                const float xv = Xq[cur][i][lane];
                dac += xv * Zq[cur][i][lane];
                wac += wbs[i] * xv;
            }
        } else if (wid == 5) {
#pragma unroll
            for (int i = 0; i < 32; i++) {
                const float xv = Xk[cur][i][lane];
                dac += xv * Zk[cur][i][lane];
                wac += wbs[i] * xv;
            }
        }
        if (e < 11) { SC_ST(nxt); }
        __syncthreads();
    }

    if (wid < 4) {
#pragma unroll
        for (int a = 0; a < 4; a++)
            *(float4*)&Sh[ihalf][ccg + 8 * a][d0c] =
                make_float4(s[a][0], s[a][1], s[a][2], s[a][3]);
    }
    __syncthreads();

    float* sp = g_spart + (size_t)((b * HEADS + h) * 12 + blockIdx.x) * 1152;
    {
        const int eidx = t * 4;
        const float* s0 = &Sh[0][0][0];
        const float* s1 = &Sh[1][0][0];
        float4 a = *(const float4*)(s0 + eidx);
        float4 c = *(const float4*)(s1 + eidx);
        sp[eidx + 0] = a.x + c.x;
        sp[eidx + 1] = a.y + c.y;
        sp[eidx + 2] = a.z + c.z;
        sp[eidx + 3] = a.w + c.w;
    }
    if (wid == 4) { sp[1024 + lane] = dac; sp[1088 + lane] = wac; }
    if (wid == 5) { sp[1056 + lane] = dac; sp[1120 + lane] = wac; }
}

// ---------------------------------------------------------------------------
// K4 (fused, split, wide): grid (HEADS, BATCH, 2), 512 thr.
// ---------------------------------------------------------------------------
__global__ __launch_bounds__(512) void softmax_mmix_kernel(const float* __restrict__ temp)
{
    __shared__ float sS[1024];
    __shared__ float snq[32], snk[32], swq[32], swk[32];
    __shared__ float att[32][32];

    const int h = blockIdx.x, b = blockIdx.y;
    const int oh = blockIdx.z;
    const int t = threadIdx.x;
    const float b2 = g_c[0];
    const float* sp = g_spart + (size_t)((b * HEADS + h) * 12) * 1152;

    const int o = oh * 96 + (t < 96 ? t : 0);
    float pwr[32];
    if (t < 96) {
#pragma unroll
        for (int cc = 0; cc < 32; cc++)
            pwr[cc] = g_pwT[(cc * HEADS + h) * CH + o];
    }

    // Reduction: 512 threads x 2 elements.
    {
        float a0 = 0.f, a1 = 0.f;
#pragma unroll
        for (int s = 0; s < 12; s++) {
            a0 += sp[s * 1152 + t];
            a1 += sp[s * 1152 + t + 512];
        }
        sS[t] = a0;
        if (t + 512 < 1024) sS[t + 512] = a1;
    }
    if (t < 64) {
        float d = 0.f, wv = 0.f;
        const int od = 1024 + t, ow = 1088 + t;
#pragma unroll
        for (int s = 0; s < 12; s++) { d += sp[s * 1152 + od]; wv += sp[s * 1152 + ow]; }
        const float n2 = d + 2.f * wv + 24.f * b2;
        const float r = fmaxf(sqrtf(fmaxf(n2, 0.f)), EPSN);
        if (t < 32) { snq[t] = r; swq[t] = wv; }
        else        { snk[t - 32] = r; swk[t - 32] = wv; }
    }
    __syncthreads();

    const int w = t >> 5, lane = t & 31;
    const float tv = temp[h];

    if (w < 8) {
        for (int r = 0; r < 4; r++) {
            const int c = w * 4 + r;
            const float Sfull = sS[c * 32 + lane] + swq[c] + swk[lane] + 24.f * b2;
            float L = Sfull / (snq[c] * snk[lane]) * tv;
            float mx = L;
#pragma unroll
            for (int oo = 16; oo > 0; oo >>= 1) mx = fmaxf(mx, __shfl_xor_sync(0xffffffffu, mx, oo));
            const float ev = expf(L - mx);
            float sm = ev;
#pragma unroll
            for (int oo = 16; oo > 0; oo >>= 1) sm += __shfl_xor_sync(0xffffffffu, sm, oo);
            att[c][lane] = ev / sm;
        }
    }
    __syncthreads();

    if (t < 96) {
        float s[32];
#pragma unroll
        for (int d = 0; d < 32; d++) s[d] = 0.f;
#pragma unroll 8
        for (int cc = 0; cc < 32; cc++) {
            const float v = pwr[cc];
#pragma unroll
            for (int d4 = 0; d4 < 8; d4++) {
                const float4 a = *(const float4*)&att[cc][d4 * 4];
                s[d4 * 4 + 0] += v * a.x;
                s[d4 * 4 + 1] += v * a.y;
                s[d4 * 4 + 2] += v * a.z;
                s[d4 * 4 + 3] += v * a.w;
            }
        }
        float* Mb = g_M + (size_t)b * CH * CH + (size_t)o * CH + h * HD;
#pragma unroll
        for (int d = 0; d < 32; d++) Mb[d] = s[d];
    }
}

// ---------------------------------------------------------------------------
// K6a (t_gemm): T[b][o][e*192+c] = sum_k M[o,k] * X[c, 576e+384+k]
// BM=96 (c rows, split by blockIdx.y), BN=96 (o cols), K=192. grid (48, 2, 8).
// ---------------------------------------------------------------------------
__global__ __launch_bounds__(256, 2) void t_gemm(const float* __restrict__ x)
{
    __shared__ unsigned As[2][96 * 20];
    __shared__ unsigned Bs[2][96 * 20];

    const int b  = blockIdx.z;
    const int e  = blockIdx.x >> 1;
    const int oB = (blockIdx.x & 1) * 96;
    const int ch = blockIdx.y;
    const int t  = threadIdx.x;
    const int wid = t >> 5, lane = t & 31;
    const int wm = wid & 1, wn = wid >> 1;
    const int gid = lane >> 2, tid4 = lane & 3;

    const float* Asrc = x + (size_t)b * CH * NVOX + (size_t)(ch * 96) * NVOX + 576 * e + 384;
    const float* Bsrc = g_M + (size_t)b * CH * CH + (size_t)oB * CH;
    float* Tb = g_V + (size_t)b * TSTRIDE;

    const uint32_t sAs = smem_u32(As);
    const uint32_t sBs = smem_u32(Bs);
    const uint32_t aoff = (uint32_t)((((lane & 7) + ((lane >> 3) & 1) * 8) * 20 +
                                      ((lane >> 4) * 4)) * 4);
    const uint32_t boff = (uint32_t)(((lane & 7) * 20 + ((lane >> 3) & 1) * 4) * 4);

    float acc[3][3][4];
#pragma unroll
    for (int i = 0; i < 3; i++)
#pragma unroll
        for (int q = 0; q < 3; q++)
#pragma unroll
            for (int r = 0; r < 4; r++) acc[i][q][r] = 0.f;

    float4 ar[2], br[2];
#define LDA_T2(K0) { _Pragma("unroll") for (int l = 0; l < 2; l++) {                     \
                       const int idx = l * 256 + t;                                      \
                       if (idx < 384)                                                    \
                         ar[l] = *(const float4*)(Asrc + (size_t)(idx >> 2) * NVOX + (K0) + (idx & 3) * 4); } }
#define LDB_T2(K0) { _Pragma("unroll") for (int l = 0; l < 2; l++) {                     \
                       const int idx = l * 256 + t;                                      \
                       if (idx < 384)                                                    \
                         br[l] = *(const float4*)(Bsrc + (size_t)(idx >> 2) * CH + (K0) + (idx & 3) * 4); } }
#define STA_T2(ST) { _Pragma("unroll") for (int l = 0; l < 2; l++) {                     \
                       const int idx = l * 256 + t;                                      \
                       if (idx < 384) {                                                  \
                         unsigned* d = &As[ST][(idx >> 2) * 20 + (idx & 3) * 4];         \
                         d[0]=f2tf(ar[l].x); d[1]=f2tf(ar[l].y); d[2]=f2tf(ar[l].z); d[3]=f2tf(ar[l].w); } } }
#define STB_T2(ST) { _Pragma("unroll") for (int l = 0; l < 2; l++) {                     \
                       const int idx = l * 256 + t;                                      \
                       if (idx < 384) {                                                  \
                         unsigned* d = &Bs[ST][(idx >> 2) * 20 + (idx & 3) * 4];         \
                         d[0]=f2tf(br[l].x); d[1]=f2tf(br[l].y); d[2]=f2tf(br[l].z); d[3]=f2tf(br[l].w); } } }

    LDA_T2(0); LDB_T2(0);
    STA_T2(0); STB_T2(0);
    LDA_T2(16); LDB_T2(16);
    __syncthreads();

    for (int it = 0; it < 12; it++) {
        const int st = it & 1;
        if (it < 11) { STA_T2(st ^ 1); STB_T2(st ^ 1); }
        if (it < 10) { LDA_T2(16 * (it + 2)); LDB_T2(16 * (it + 2)); }

        const uint32_t aBase = sAs + (uint32_t)(st * 1920 * 4) + aoff;
        const uint32_t bBase = sBs + (uint32_t)(st * 1920 * 4) + boff;
#pragma unroll
        for (int h = 0; h < 2; h++) {
            const int kk = h * 8;
            unsigned af[3][4], bf[3][2];
#pragma unroll
            for (int mt = 0; mt < 3; mt++) {
                const int r0 = wm * 48 + mt * 16;
                ldsm_x4(af[mt], aBase + (uint32_t)((r0 * 20 + kk) * 4));
            }
#pragma unroll
            for (int nt = 0; nt < 3; nt++) {
                const int c0 = wn * 24 + nt * 8;
                ldsm_x2(bf[nt], bBase + (uint32_t)((c0 * 20 + kk) * 4));
            }
#pragma unroll
            for (int mt = 0; mt < 3; mt++)
#pragma unroll
                for (int nt = 0; nt < 3; nt++)
                    mma_tf32(acc[mt][nt], af[mt], bf[nt]);
        }
        __syncthreads();
    }

#pragma unroll
    for (int mt = 0; mt < 3; mt++) {
        const int c0 = ch * 96 + wm * 48 + mt * 16 + gid;
#pragma unroll
        for (int nt = 0; nt < 3; nt++) {
            const int o0 = oB + wn * 24 + nt * 8 + 2 * tid4;
            float* p0 = Tb + (size_t)o0 * 4608 + e * 192;
            float* p1 = Tb + (size_t)(o0 + 1) * 4608 + e * 192;
            p0[c0]     = acc[mt][nt][0];
            p1[c0]     = acc[mt][nt][1];
            p0[c0 + 8] = acc[mt][nt][2];
            p1[c0 + 8] = acc[mt][nt][3];
        }
    }
}

// ---------------------------------------------------------------------------
// K6b (y_gemm): y[o][24a+e] = sum_c W[a,c]*T[o][e*192+c] + msum[o]*beta[a] + pbias[o]
// BM=192, BN=96 (4 o x 24 e), K=192. grid (48, 3, 8).
// ---------------------------------------------------------------------------
__global__ __launch_bounds__(256, 2) void y_gemm(float* __restrict__ y,
                                                 const float* __restrict__ qkv_w,
                                                 const float* __restrict__ qkv_b,
                                                 const float* __restrict__ pbias)
{
    __shared__ unsigned As[2][192 * 20];
    __shared__ unsigned Bs[2][96 * 20];

    const int b  = blockIdx.z;
    const int m0 = blockIdx.y * 192;
    const int cb = blockIdx.x;
    const int t  = threadIdx.x;
    const int wid = t >> 5, lane = t & 31;
    const int wm = wid & 3, wn = wid >> 2;
    const int gid = lane >> 2, tid4 = lane & 3;

    const float* Asrc = qkv_w + (size_t)m0 * CH;
    const float* Tb = g_V + (size_t)b * TSTRIDE + (size_t)cb * 4 * 4608;
    float* yb = y + (size_t)b * CH * NVOX;

    const uint32_t sAs = smem_u32(As);
    const uint32_t sBs = smem_u32(Bs);
    const uint32_t aoff = (uint32_t)((((lane & 7) + ((lane >> 3) & 1) * 8) * 20 +
                                      ((lane >> 4) * 4)) * 4);
    const uint32_t boff = (uint32_t)(((lane & 7) * 20 + ((lane >> 3) & 1) * 4) * 4);

    float acc[3][6][4];
#pragma unroll
    for (int i = 0; i < 3; i++)
#pragma unroll
        for (int q = 0; q < 6; q++)
#pragma unroll
            for (int r = 0; r < 4; r++) acc[i][q][r] = 0.f;

    float4 ar[3], br[2];
#define LDA_Y(K0) { _Pragma("unroll") for (int l = 0; l < 3; l++) {                      \
                      const int idx = l * 256 + t;                                       \
                      ar[l] = *(const float4*)(Asrc + (size_t)(idx >> 2) * CH + (K0) + (idx & 3) * 4); } }
#define LDB_Y(K0) { _Pragma("unroll") for (int l = 0; l < 2; l++) {                      \
                      const int idx = l * 256 + t;                                       \
                      if (idx < 384) {                                                   \
                        const int jj = idx >> 2;                                         \
                        br[l] = *(const float4*)(Tb + (size_t)(jj / 24) * 4608 +         \
                                                 (jj % 24) * 192 + (K0) + (idx & 3) * 4); } } }
#define STA_Y(ST) { _Pragma("unroll") for (int l = 0; l < 3; l++) {                      \
                      const int idx = l * 256 + t;                                       \
                      unsigned* d = &As[ST][(idx >> 2) * 20 + (idx & 3) * 4];            \
                      d[0]=f2tf(ar[l].x); d[1]=f2tf(ar[l].y); d[2]=f2tf(ar[l].z); d[3]=f2tf(ar[l].w); } }
#define STB_Y(ST) { _Pragma("unroll") for (int l = 0; l < 2; l++) {                      \
                      const int idx = l * 256 + t;                                       \
                      if (idx < 384) {                                                   \
                        unsigned* d = &Bs[ST][(idx >> 2) * 20 + (idx & 3) * 4];          \
                        d[0]=f2tf(br[l].x); d[1]=f2tf(br[l].y); d[2]=f2tf(br[l].z); d[3]=f2tf(br[l].w); } } }

    LDA_Y(0); LDB_Y(0);
    STA_Y(0); STB_Y(0);
    LDA_Y(16); LDB_Y(16);
    __syncthreads();

    for (int it = 0; it < 12; it++) {
        const int st = it & 1;
        if (it < 11) { STA_Y(st ^ 1); STB_Y(st ^ 1); }
        if (it < 10) { LDA_Y(16 * (it + 2)); LDB_Y(16 * (it + 2)); }

        const uint32_t aBase = sAs + (uint32_t)(st * 3840 * 4) + aoff;
        const uint32_t bBase = sBs + (uint32_t)(st * 1920 * 4) + boff;
#pragma unroll
        for (int h = 0; h < 2; h++) {
            const int kk = h * 8;
            unsigned af[3][4], bf[6][2];
#pragma unroll
            for (int mt = 0; mt < 3; mt++) {
                const int r0 = wm * 48 + mt * 16;
                ldsm_x4(af[mt], aBase + (uint32_t)((r0 * 20 + kk) * 4));
            }
#pragma unroll
            for (int nt = 0; nt < 6; nt++) {
                const int c0 = wn * 48 + nt * 8;
                ldsm_x2(bf[nt], bBase + (uint32_t)((c0 * 20 + kk) * 4));
            }
#pragma unroll
            for (int mt = 0; mt < 3; mt++)
#pragma unroll
                for (int nt = 0; nt < 6; nt++)
                    mma_tf32(acc[mt][nt], af[mt], bf[nt]);
        }
        __syncthreads();
    }

#pragma unroll
    for (int mt = 0; mt < 3; mt++) {
        const int r0 = wm * 48 + mt * 16 + gid;
        const int a0 = m0 + r0;
        const float be0 = qkv_b[a0], be1 = qkv_b[a0 + 8];
#pragma unroll
        for (int nt = 0; nt < 6; nt++) {
            const int j0 = wn * 48 + nt * 8 + 2 * tid4;
            const int o  = cb * 4 + j0 / 24;
            const int e  = j0 % 24;
            const float ms = g_msum[o];
            const float pb = pbias[o];
            const float bias0 = ms * be0 + pb;
            const float bias1 = ms * be1 + pb;
            *(float2*)(yb + (size_t)o * NVOX + 24 * a0 + e) =
                make_float2(acc[mt][nt][0] + bias0, acc[mt][nt][1] + bias0);
            *(float2*)(yb + (size_t)o * NVOX + 24 * (a0 + 8) + e) =
                make_float2(acc[mt][nt][2] + bias1, acc[mt][nt][3] + bias1);
        }
    }
}

// ---------------------------------------------------------------------------
extern "C" void kernel_launch(void* const* d_in, const int* in_sizes, int n_in,
                              void* d_out, int out_size)
{
    const float* x      = (const float*)d_in[0];
    const float* qkv_w  = (const float*)d_in[1];
    const float* qkv_b  = (const float*)d_in[2];
    const float* temp   = (const float*)d_in[3];
    const float* proj_w = (const float*)d_in[4];
    const float* proj_b = (const float*)d_in[5];
    float* y = (float*)d_out;

    pre_kernel         <<<73, 256>>>(qkv_w, qkv_b, proj_w);
    z_gemm             <<<dim3(96, 1, BATCH), 256>>>(x);
    scores_kernel      <<<dim3(12, HEADS, BATCH), 256>>>(x);
    softmax_mmix_kernel<<<dim3(HEADS, BATCH, 2), 512>>>(temp);
    t_gemm             <<<dim3(48, 2, BATCH), 256>>>(x);
    y_gemm             <<<dim3(48, 3, BATCH), 256>>>(y, qkv_w, qkv_b, proj_b);
}